// round 12
// baseline (speedup 1.0000x reference)
#include <cuda_runtime.h>
#include <cuda_bf16.h>
#include <stdint.h>
#include <math.h>

// ---------------- problem constants ----------------
#define KD    512
#define TOPK  4
#define ROW_ELEMS 8192
#define NB 4096
#define NP 4096
#define CAND 16
#define NTILE (NP/128)       // 32 column tiles
#define NWORK (NB*TOPK)      // 16384 gather work items

// ---------------- GEMM tiling ----------------
#define BM 128
#define BN 128
#define BK 32
#define STAGES 3
#define NKT (KD/BK)          // 16 k-steps
#define A_STAGE_BYTES (BM*BK*2)   // 8192
#define B_STAGE_BYTES (BN*BK*2)   // 8192

// ---------------- device scratch ----------------
__device__ float g_invk[NP];
__device__ unsigned g_tilecand[(size_t)NB * NTILE * 4];  // 2 MB, u32 keys
__device__ int   g_topidx[NWORK];
__device__ int   g_binCount[NP];
__device__ int   g_binStart[NP];
__device__ int   g_order[NWORK];
__device__ __nv_bfloat16 g_Xb[(size_t)NB * KD];      // 4 MB
__device__ __nv_bfloat16 g_Kb[(size_t)NP * KD];      // 4 MB (pre-scaled by invk)

// ---------------- helpers ----------------
__device__ __forceinline__ uint32_t smem_to_u32(const void* p) {
    uint32_t a;
    asm("{ .reg .u64 t; cvta.to.shared.u64 t, %1; cvt.u32.u64 %0, t; }" : "=r"(a) : "l"(p));
    return a;
}
__device__ __forceinline__ void cp16(uint32_t dst, const void* src) {
    asm volatile("cp.async.cg.shared.global [%0], [%1], 16;" :: "r"(dst), "l"(src) : "memory");
}
#define CP_COMMIT() asm volatile("cp.async.commit_group;" ::: "memory")
#define CP_WAIT1()  asm volatile("cp.async.wait_group 1;" ::: "memory")
#define CP_WAIT0()  asm volatile("cp.async.wait_group 0;" ::: "memory")

__device__ __forceinline__ void ldm4(uint32_t* r, uint32_t a) {
    asm volatile("ldmatrix.sync.aligned.m8n8.x4.shared.b16 {%0,%1,%2,%3}, [%4];"
                 : "=r"(r[0]), "=r"(r[1]), "=r"(r[2]), "=r"(r[3]) : "r"(a));
}
__device__ __forceinline__ void mma16816(float* c, const uint32_t* a, uint32_t b0, uint32_t b1) {
    asm volatile("mma.sync.aligned.m16n8k16.row.col.f32.bf16.bf16.f32 "
                 "{%0,%1,%2,%3}, {%4,%5,%6,%7}, {%8,%9}, {%0,%1,%2,%3};"
                 : "+f"(c[0]), "+f"(c[1]), "+f"(c[2]), "+f"(c[3])
                 : "r"(a[0]), "r"(a[1]), "r"(a[2]), "r"(a[3]), "r"(b0), "r"(b1));
}

// sortable-ascending float map (smallest cos first)
__device__ __forceinline__ unsigned fmap(float v) {
    unsigned u = __float_as_uint(v);
    return (u & 0x80000000u) ? ~u : (u | 0x80000000u);
}

// ---- u32 sorted small-list primitives (ascending, keep smallest) ----
__device__ __forceinline__ void insert4(unsigned (&a)[4], unsigned key) {
    if (key < a[3]) {
        a[3] = key;
        #pragma unroll
        for (int q = 3; q > 0; q--)
            if (a[q] < a[q - 1]) { unsigned t = a[q]; a[q] = a[q - 1]; a[q - 1] = t; }
    }
}
__device__ __forceinline__ void merge4(unsigned (&a)[4], const unsigned (&b)[4]) {
    #pragma unroll
    for (int q = 0; q < 4; q++) { unsigned o = b[3 - q]; if (o < a[q]) a[q] = o; }
    #pragma unroll
    for (int kk = 2; kk >= 1; kk >>= 1)
        #pragma unroll
        for (int i = 0; i < 4; i++)
            if (!(i & kk)) { int j = i | kk; if (a[j] < a[i]) { unsigned t = a[i]; a[i] = a[j]; a[j] = t; } }
}
__device__ __forceinline__ void insert16(unsigned (&a)[16], unsigned key) {
    if (key < a[15]) {
        a[15] = key;
        #pragma unroll
        for (int q = 15; q > 0; q--)
            if (a[q] < a[q - 1]) { unsigned t = a[q]; a[q] = a[q - 1]; a[q - 1] = t; }
    }
}
__device__ __forceinline__ void merge16(unsigned (&a)[16], const unsigned (&b)[16]) {
    #pragma unroll
    for (int q = 0; q < 16; q++) { unsigned o = b[15 - q]; if (o < a[q]) a[q] = o; }
    #pragma unroll
    for (int kk = 8; kk >= 1; kk >>= 1)
        #pragma unroll
        for (int i = 0; i < 16; i++)
            if (!(i & kk)) { int j = i | kk; if (a[j] < a[i]) { unsigned t = a[i]; a[i] = a[j]; a[j] = t; } }
}

__device__ __forceinline__ unsigned pack_bf16(float a, float b) {
    __nv_bfloat16 ha = __float2bfloat16_rn(a);
    __nv_bfloat16 hb = __float2bfloat16_rn(b);
    unsigned short ua = *(unsigned short*)&ha;
    unsigned short ub = *(unsigned short*)&hb;
    return (unsigned)ua | ((unsigned)ub << 16);
}

// ---------------- kernel 1: fused converts + histogram zero --------------
__global__ void convert_all_kernel(const float* __restrict__ x, const float* __restrict__ keys) {
    if (blockIdx.x < 1024) {
        int i = blockIdx.x * 256 + threadIdx.x;
        const float* s = x + (size_t)i * 8;
        float4 f0 = *(const float4*)s;
        float4 f1 = *(const float4*)(s + 4);
        uint4 o;
        o.x = pack_bf16(f0.x, f0.y); o.y = pack_bf16(f0.z, f0.w);
        o.z = pack_bf16(f1.x, f1.y); o.w = pack_bf16(f1.z, f1.w);
        ((uint4*)g_Xb)[i] = o;
    } else if (blockIdx.x < 1536) {
        const int wid = threadIdx.x >> 5, lane = threadIdx.x & 31;
        const int row = (blockIdx.x - 1024) * 8 + wid;
        const float* kr = keys + (size_t)row * KD;
        float4 v[4];
        float s = 0.f;
        #pragma unroll
        for (int c4 = 0; c4 < 4; c4++) {
            v[c4] = *(const float4*)(kr + c4 * 128 + lane * 4);
            s = fmaf(v[c4].x, v[c4].x, s);
            s = fmaf(v[c4].y, v[c4].y, s);
            s = fmaf(v[c4].z, v[c4].z, s);
            s = fmaf(v[c4].w, v[c4].w, s);
        }
        #pragma unroll
        for (int o = 16; o; o >>= 1) s += __shfl_xor_sync(0xffffffffu, s, o);
        double d = (double)fmaxf(s, 1e-12f);
        float iv = (float)(1.0 / sqrt(d));
        if (lane == 0) g_invk[row] = iv;
        uint2* dst = (uint2*)(g_Kb + (size_t)row * KD);
        #pragma unroll
        for (int c4 = 0; c4 < 4; c4++) {
            uint2 o;
            o.x = pack_bf16(v[c4].x * iv, v[c4].y * iv);
            o.y = pack_bf16(v[c4].z * iv, v[c4].w * iv);
            dst[(c4 * 128 + lane * 4) >> 2] = o;
        }
    } else {
        int i = (blockIdx.x - 1536) * 256 + threadIdx.x;
        if (i < NP) g_binCount[i] = 0;
    }
}

// ---------------- kernel 2: coarse bf16 HMMA GEMM + fused per-tile top-4 ----
__global__ void __launch_bounds__(256, 2) coarse_gemm() {
    __shared__ __align__(1024) char sA[STAGES][A_STAGE_BYTES];
    __shared__ __align__(1024) char sB[STAGES][B_STAGE_BYTES];
    const uint32_t aU = smem_to_u32(sA);
    const uint32_t bU = smem_to_u32(sB);
    const int t = threadIdx.x;
    const int rowbase = blockIdx.y * BM;
    const int colbase = blockIdx.x * BN;

    const int r0 = t >> 2, c0 = t & 3;
    const int r1 = (t + 256) >> 2, c1 = (t + 256) & 3;
    const uint32_t sOffA0 = r0 * 64 + (c0 ^ ((r0 >> 1) & 3)) * 16;
    const uint32_t sOffA1 = r1 * 64 + (c1 ^ ((r1 >> 1) & 3)) * 16;
    const __nv_bfloat16* gA0 = g_Xb + (size_t)(rowbase + r0) * KD + c0 * 8;
    const __nv_bfloat16* gA1 = g_Xb + (size_t)(rowbase + r1) * KD + c1 * 8;
    const __nv_bfloat16* gB0 = g_Kb + (size_t)(colbase + r0) * KD + c0 * 8;
    const __nv_bfloat16* gB1 = g_Kb + (size_t)(colbase + r1) * KD + c1 * 8;

    const int wid = t >> 5, lane = t & 31;
    const int wm = wid & 3, wn = wid >> 2;

    uint32_t offA[2][2];
    uint32_t offB[2][4];
    #pragma unroll
    for (int s = 0; s < 2; s++) {
        #pragma unroll
        for (int mt = 0; mt < 2; mt++) {
            int row = wm * 32 + mt * 16 + (lane & 15);
            int cL = 2 * s + (lane >> 4);
            offA[s][mt] = row * 64 + (cL ^ ((row >> 1) & 3)) * 16;
        }
        #pragma unroll
        for (int np = 0; np < 4; np++) {
            int nrow = wn * 64 + np * 16 + (lane & 7) + ((lane >> 4) << 3);
            int cL = 2 * s + ((lane >> 3) & 1);
            offB[s][np] = nrow * 64 + (cL ^ ((nrow >> 1) & 3)) * 16;
        }
    }

    auto load_stage = [&](int st, int kt) {
        const int k0 = kt * BK;
        cp16(aU + st * A_STAGE_BYTES + sOffA0, gA0 + k0);
        cp16(aU + st * A_STAGE_BYTES + sOffA1, gA1 + k0);
        cp16(bU + st * B_STAGE_BYTES + sOffA0, gB0 + k0);
        cp16(bU + st * B_STAGE_BYTES + sOffA1, gB1 + k0);
    };

    load_stage(0, 0); CP_COMMIT();
    load_stage(1, 1); CP_COMMIT();

    float acc[2][8][4];
    #pragma unroll
    for (int mt = 0; mt < 2; mt++)
        #pragma unroll
        for (int nt = 0; nt < 8; nt++)
            #pragma unroll
            for (int q = 0; q < 4; q++) acc[mt][nt][q] = 0.f;

    int st = 0, stLoad = 2;
    for (int kt = 0; kt < NKT; kt++) {
        CP_WAIT1();
        __syncthreads();
        const int nk = kt + STAGES - 1;
        if (nk < NKT) load_stage(stLoad, nk);
        CP_COMMIT();

        const uint32_t aS = aU + st * A_STAGE_BYTES;
        const uint32_t bS = bU + st * B_STAGE_BYTES;

        #pragma unroll
        for (int s = 0; s < 2; s++) {
            uint32_t ar[2][4];
            #pragma unroll
            for (int mt = 0; mt < 2; mt++) ldm4(ar[mt], aS + offA[s][mt]);
            uint32_t br[4][4];
            #pragma unroll
            for (int np = 0; np < 4; np++) ldm4(br[np], bS + offB[s][np]);
            #pragma unroll
            for (int mt = 0; mt < 2; mt++)
                #pragma unroll
                for (int np = 0; np < 4; np++) {
                    mma16816(acc[mt][np * 2 + 0], ar[mt], br[np][0], br[np][1]);
                    mma16816(acc[mt][np * 2 + 1], ar[mt], br[np][2], br[np][3]);
                }
        }
        st = (st == STAGES - 1) ? 0 : st + 1;
        stLoad = (stLoad == STAGES - 1) ? 0 : stLoad + 1;
    }

    CP_WAIT0();
    __syncthreads();
    unsigned* cbuf = (unsigned*)sA;

    const int g = lane >> 2;
    const int sub = lane & 3;

    #pragma unroll
    for (int mt = 0; mt < 2; mt++) {
        #pragma unroll
        for (int h = 0; h < 2; h++) {
            unsigned a4[4];
            #pragma unroll
            for (int q = 0; q < 4; q++) a4[q] = 0xFFFFFFFFu;
            #pragma unroll
            for (int nt = 0; nt < 8; nt++) {
                #pragma unroll
                for (int j = 0; j < 2; j++) {
                    float v = acc[mt][nt][2 * h + j];
                    unsigned col = (unsigned)(colbase + wn * 64 + nt * 8 + 2 * sub + j);
                    insert4(a4, (fmap(v) & 0xFFFFF000u) | col);
                }
            }
            #pragma unroll
            for (int off = 1; off <= 2; off <<= 1) {
                unsigned b4[4];
                #pragma unroll
                for (int q = 0; q < 4; q++) b4[q] = __shfl_xor_sync(0xffffffffu, a4[q], off);
                merge4(a4, b4);
            }
            const int rloc = wm * 32 + mt * 16 + h * 8 + g;
            if (sub == 0) {
                #pragma unroll
                for (int q = 0; q < 4; q++) cbuf[(wn * 128 + rloc) * 4 + q] = a4[q];
            }
        }
    }
    __syncthreads();

    if (t < 128) {
        unsigned a4[4], b4[4];
        #pragma unroll
        for (int q = 0; q < 4; q++) { a4[q] = cbuf[t * 4 + q]; b4[q] = cbuf[(128 + t) * 4 + q]; }
        merge4(a4, b4);
        uint4* dst = (uint4*)(g_tilecand + ((size_t)(rowbase + t) * NTILE + blockIdx.x) * 4);
        *dst = make_uint4(a4[0], a4[1], a4[2], a4[3]);
    }
}

// ---------------- kernel 3: merge + exact rescore (1 warp/cand) + top-4 ---
__global__ void __launch_bounds__(512) select_kernel(const float* __restrict__ x, const float* __restrict__ keys) {
    const int row = blockIdx.x;
    __shared__ float xs[KD];
    __shared__ int cidx[CAND];
    __shared__ unsigned long long ck[CAND];
    const int tid = threadIdx.x, wid = tid >> 5, lane = tid & 31;

    xs[tid] = x[(size_t)row * KD + tid];

    if (wid == 0) {
        unsigned a[16];
        #pragma unroll
        for (int q = 0; q < 16; q++) a[q] = 0xFFFFFFFFu;
        uint4 v = *(const uint4*)(g_tilecand + ((size_t)row * NTILE + lane) * 4);
        insert16(a, v.x); insert16(a, v.y); insert16(a, v.z); insert16(a, v.w);
        #pragma unroll
        for (int off = 16; off; off >>= 1) {
            unsigned b[16];
            #pragma unroll
            for (int q = 0; q < 16; q++) b[q] = __shfl_xor_sync(0xffffffffu, a[q], off);
            merge16(a, b);
        }
        if (lane < 16) cidx[lane] = (int)(a[lane] & 0xFFFu);
    }
    __syncthreads();

    // one warp per candidate: all 16 key rows in flight simultaneously
    {
        const int idx = cidx[wid];
        const float* kr = keys + (size_t)idx * KD;
        float sum = 0.f;
        #pragma unroll
        for (int j = 0; j < 16; j++) sum = fmaf(xs[lane + 32 * j], kr[lane + 32 * j], sum);
        #pragma unroll
        for (int o = 16; o; o >>= 1) sum += __shfl_xor_sync(0xffffffffu, sum, o);
        if (lane == 0) {
            float sc = sum * g_invk[idx];
            ck[wid] = ((unsigned long long)fmap(sc) << 32) | (unsigned)idx;
        }
    }
    __syncthreads();
    if (tid == 0) {
        #pragma unroll
        for (int q = 0; q < TOPK; q++) {
            unsigned long long best = ~0ull; int bi = 0;
            #pragma unroll
            for (int c = 0; c < CAND; c++) if (ck[c] < best) { best = ck[c]; bi = c; }
            ck[bi] = ~0ull;
            int idx = (int)(best & 0xffffffffu);
            g_topidx[row * TOPK + q] = idx;
            atomicAdd(&g_binCount[idx], 1);
        }
    }
}

// ---------------- kernel 4: fused scan + scatter (one block) --------------
__global__ void scan_scatter_kernel() {
    __shared__ int ssum[1024];
    const int t = threadIdx.x;
    int4 v = ((const int4*)g_binCount)[t];
    int s = v.x + v.y + v.z + v.w;
    ssum[t] = s;
    __syncthreads();
    for (int off = 1; off < 1024; off <<= 1) {
        int other = 0;
        if (t >= off) other = ssum[t - off];
        __syncthreads();
        if (t >= off) ssum[t] += other;
        __syncthreads();
    }
    int excl = ssum[t] - s;
    int4 st;
    st.x = excl;
    st.y = excl + v.x;
    st.z = excl + v.x + v.y;
    st.w = excl + v.x + v.y + v.z;
    ((int4*)g_binStart)[t] = st;
    __syncthreads();
    // scatter (same block; __syncthreads makes g_binStart visible block-wide)
    for (int w = t; w < NWORK; w += 1024) {
        int idx = g_topidx[w];
        int pos = atomicAdd(&g_binStart[idx], 1);
        g_order[pos] = w;
    }
}

// ---------------- kernel 5: index-sorted gather ---------------------------
__global__ void gather_kernel(const float* __restrict__ pv, float* __restrict__ out) {
    const int w = g_order[blockIdx.x];
    const int idx = g_topidx[w];
    const float4* src = (const float4*)(pv + (size_t)idx * ROW_ELEMS);
    float4* dst = (float4*)(out + (size_t)w * ROW_ELEMS);
    #pragma unroll 8
    for (int i = threadIdx.x; i < ROW_ELEMS / 4; i += 256)
        __stcs(dst + i, __ldg(src + i));
}

// ---------------- launcher ----------------
extern "C" void kernel_launch(void* const* d_in, const int* in_sizes, int n_in,
                              void* d_out, int out_size) {
    const float* x    = (const float*)d_in[0];   // (4096, 512)
    const float* keys = (const float*)d_in[1];   // (4096, 512)
    const float* pv   = (const float*)d_in[2];   // (4096, 16, 512)
    float* out = (float*)d_out;

    convert_all_kernel<<<1024 + NP / 8 + 16, 256>>>(x, keys);
    coarse_gemm<<<dim3(NP / BN, NB / BM), 256>>>();
    select_kernel<<<NB, 512>>>(x, keys);
    scan_scatter_kernel<<<1, 1024>>>();
    gather_kernel<<<NWORK, 256>>>(pv, out);
}

// round 13
// speedup vs baseline: 1.0416x; 1.0416x over previous
#include <cuda_runtime.h>
#include <cuda_bf16.h>
#include <stdint.h>
#include <math.h>

// ---------------- problem constants ----------------
#define KD    512
#define TOPK  4
#define ROW_ELEMS 8192
#define NB 4096
#define NP 4096
#define CAND 16
#define NTILE (NP/128)       // 32 column tiles
#define NWORK (NB*TOPK)      // 16384 gather work items

// ---------------- GEMM tiling ----------------
#define BM 128
#define BN 128
#define BK 32
#define STAGES 3
#define NKT (KD/BK)          // 16 k-steps
#define A_STAGE_BYTES (BM*BK*2)   // 8192
#define B_STAGE_BYTES (BN*BK*2)   // 8192

// ---------------- device scratch ----------------
__device__ float g_invk[NP];
__device__ unsigned g_tilecand[(size_t)NB * NTILE * 4];  // 2 MB, u32 keys
__device__ int   g_topidx[NWORK];
__device__ int   g_binCount[NP];
__device__ int   g_binStart[NP];
__device__ int   g_order[NWORK];
__device__ __nv_bfloat16 g_Xb[(size_t)NB * KD];      // 4 MB
__device__ __nv_bfloat16 g_Kb[(size_t)NP * KD];      // 4 MB (pre-scaled by invk)

// ---------------- helpers ----------------
__device__ __forceinline__ uint32_t smem_to_u32(const void* p) {
    uint32_t a;
    asm("{ .reg .u64 t; cvta.to.shared.u64 t, %1; cvt.u32.u64 %0, t; }" : "=r"(a) : "l"(p));
    return a;
}
__device__ __forceinline__ void cp16(uint32_t dst, const void* src) {
    asm volatile("cp.async.cg.shared.global [%0], [%1], 16;" :: "r"(dst), "l"(src) : "memory");
}
#define CP_COMMIT() asm volatile("cp.async.commit_group;" ::: "memory")
#define CP_WAIT1()  asm volatile("cp.async.wait_group 1;" ::: "memory")
#define CP_WAIT0()  asm volatile("cp.async.wait_group 0;" ::: "memory")

__device__ __forceinline__ void ldm4(uint32_t* r, uint32_t a) {
    asm volatile("ldmatrix.sync.aligned.m8n8.x4.shared.b16 {%0,%1,%2,%3}, [%4];"
                 : "=r"(r[0]), "=r"(r[1]), "=r"(r[2]), "=r"(r[3]) : "r"(a));
}
__device__ __forceinline__ void mma16816(float* c, const uint32_t* a, uint32_t b0, uint32_t b1) {
    asm volatile("mma.sync.aligned.m16n8k16.row.col.f32.bf16.bf16.f32 "
                 "{%0,%1,%2,%3}, {%4,%5,%6,%7}, {%8,%9}, {%0,%1,%2,%3};"
                 : "+f"(c[0]), "+f"(c[1]), "+f"(c[2]), "+f"(c[3])
                 : "r"(a[0]), "r"(a[1]), "r"(a[2]), "r"(a[3]), "r"(b0), "r"(b1));
}

// sortable-ascending float map (smallest cos first)
__device__ __forceinline__ unsigned fmap(float v) {
    unsigned u = __float_as_uint(v);
    return (u & 0x80000000u) ? ~u : (u | 0x80000000u);
}

// ---- u32 sorted small-list primitives (ascending, keep smallest) ----
__device__ __forceinline__ void insert4(unsigned (&a)[4], unsigned key) {
    if (key < a[3]) {
        a[3] = key;
        #pragma unroll
        for (int q = 3; q > 0; q--)
            if (a[q] < a[q - 1]) { unsigned t = a[q]; a[q] = a[q - 1]; a[q - 1] = t; }
    }
}
__device__ __forceinline__ void merge4(unsigned (&a)[4], const unsigned (&b)[4]) {
    #pragma unroll
    for (int q = 0; q < 4; q++) { unsigned o = b[3 - q]; if (o < a[q]) a[q] = o; }
    #pragma unroll
    for (int kk = 2; kk >= 1; kk >>= 1)
        #pragma unroll
        for (int i = 0; i < 4; i++)
            if (!(i & kk)) { int j = i | kk; if (a[j] < a[i]) { unsigned t = a[i]; a[i] = a[j]; a[j] = t; } }
}
__device__ __forceinline__ void insert16(unsigned (&a)[16], unsigned key) {
    if (key < a[15]) {
        a[15] = key;
        #pragma unroll
        for (int q = 15; q > 0; q--)
            if (a[q] < a[q - 1]) { unsigned t = a[q]; a[q] = a[q - 1]; a[q - 1] = t; }
    }
}
__device__ __forceinline__ void merge16(unsigned (&a)[16], const unsigned (&b)[16]) {
    #pragma unroll
    for (int q = 0; q < 16; q++) { unsigned o = b[15 - q]; if (o < a[q]) a[q] = o; }
    #pragma unroll
    for (int kk = 8; kk >= 1; kk >>= 1)
        #pragma unroll
        for (int i = 0; i < 16; i++)
            if (!(i & kk)) { int j = i | kk; if (a[j] < a[i]) { unsigned t = a[i]; a[i] = a[j]; a[j] = t; } }
}

__device__ __forceinline__ unsigned pack_bf16(float a, float b) {
    __nv_bfloat16 ha = __float2bfloat16_rn(a);
    __nv_bfloat16 hb = __float2bfloat16_rn(b);
    unsigned short ua = *(unsigned short*)&ha;
    unsigned short ub = *(unsigned short*)&hb;
    return (unsigned)ua | ((unsigned)ub << 16);
}

// ---------------- kernel 1: fused converts + histogram zero --------------
__global__ void convert_all_kernel(const float* __restrict__ x, const float* __restrict__ keys) {
    if (blockIdx.x < 1024) {
        int i = blockIdx.x * 256 + threadIdx.x;
        const float* s = x + (size_t)i * 8;
        float4 f0 = *(const float4*)s;
        float4 f1 = *(const float4*)(s + 4);
        uint4 o;
        o.x = pack_bf16(f0.x, f0.y); o.y = pack_bf16(f0.z, f0.w);
        o.z = pack_bf16(f1.x, f1.y); o.w = pack_bf16(f1.z, f1.w);
        ((uint4*)g_Xb)[i] = o;
    } else if (blockIdx.x < 1536) {
        const int wid = threadIdx.x >> 5, lane = threadIdx.x & 31;
        const int row = (blockIdx.x - 1024) * 8 + wid;
        const float* kr = keys + (size_t)row * KD;
        float4 v[4];
        float s = 0.f;
        #pragma unroll
        for (int c4 = 0; c4 < 4; c4++) {
            v[c4] = *(const float4*)(kr + c4 * 128 + lane * 4);
            s = fmaf(v[c4].x, v[c4].x, s);
            s = fmaf(v[c4].y, v[c4].y, s);
            s = fmaf(v[c4].z, v[c4].z, s);
            s = fmaf(v[c4].w, v[c4].w, s);
        }
        #pragma unroll
        for (int o = 16; o; o >>= 1) s += __shfl_xor_sync(0xffffffffu, s, o);
        double d = (double)fmaxf(s, 1e-12f);
        float iv = (float)(1.0 / sqrt(d));
        if (lane == 0) g_invk[row] = iv;
        uint2* dst = (uint2*)(g_Kb + (size_t)row * KD);
        #pragma unroll
        for (int c4 = 0; c4 < 4; c4++) {
            uint2 o;
            o.x = pack_bf16(v[c4].x * iv, v[c4].y * iv);
            o.y = pack_bf16(v[c4].z * iv, v[c4].w * iv);
            dst[(c4 * 128 + lane * 4) >> 2] = o;
        }
    } else {
        int i = (blockIdx.x - 1536) * 256 + threadIdx.x;
        if (i < NP) g_binCount[i] = 0;
    }
}

// ---------------- kernel 2: coarse bf16 HMMA GEMM + fused per-tile top-4 ----
__global__ void __launch_bounds__(256) coarse_gemm() {
    __shared__ __align__(1024) char sA[STAGES][A_STAGE_BYTES];
    __shared__ __align__(1024) char sB[STAGES][B_STAGE_BYTES];
    const uint32_t aU = smem_to_u32(sA);
    const uint32_t bU = smem_to_u32(sB);
    const int t = threadIdx.x;
    const int rowbase = blockIdx.y * BM;
    const int colbase = blockIdx.x * BN;

    const int r0 = t >> 2, c0 = t & 3;
    const int r1 = (t + 256) >> 2, c1 = (t + 256) & 3;
    const uint32_t sOffA0 = r0 * 64 + (c0 ^ ((r0 >> 1) & 3)) * 16;
    const uint32_t sOffA1 = r1 * 64 + (c1 ^ ((r1 >> 1) & 3)) * 16;
    const __nv_bfloat16* gA0 = g_Xb + (size_t)(rowbase + r0) * KD + c0 * 8;
    const __nv_bfloat16* gA1 = g_Xb + (size_t)(rowbase + r1) * KD + c1 * 8;
    const __nv_bfloat16* gB0 = g_Kb + (size_t)(colbase + r0) * KD + c0 * 8;
    const __nv_bfloat16* gB1 = g_Kb + (size_t)(colbase + r1) * KD + c1 * 8;

    const int wid = t >> 5, lane = t & 31;
    const int wm = wid & 3, wn = wid >> 2;

    uint32_t offA[2][2];
    uint32_t offB[2][4];
    #pragma unroll
    for (int s = 0; s < 2; s++) {
        #pragma unroll
        for (int mt = 0; mt < 2; mt++) {
            int row = wm * 32 + mt * 16 + (lane & 15);
            int cL = 2 * s + (lane >> 4);
            offA[s][mt] = row * 64 + (cL ^ ((row >> 1) & 3)) * 16;
        }
        #pragma unroll
        for (int np = 0; np < 4; np++) {
            int nrow = wn * 64 + np * 16 + (lane & 7) + ((lane >> 4) << 3);
            int cL = 2 * s + ((lane >> 3) & 1);
            offB[s][np] = nrow * 64 + (cL ^ ((nrow >> 1) & 3)) * 16;
        }
    }

    auto load_stage = [&](int st, int kt) {
        const int k0 = kt * BK;
        cp16(aU + st * A_STAGE_BYTES + sOffA0, gA0 + k0);
        cp16(aU + st * A_STAGE_BYTES + sOffA1, gA1 + k0);
        cp16(bU + st * B_STAGE_BYTES + sOffA0, gB0 + k0);
        cp16(bU + st * B_STAGE_BYTES + sOffA1, gB1 + k0);
    };

    load_stage(0, 0); CP_COMMIT();
    load_stage(1, 1); CP_COMMIT();

    float acc[2][8][4];
    #pragma unroll
    for (int mt = 0; mt < 2; mt++)
        #pragma unroll
        for (int nt = 0; nt < 8; nt++)
            #pragma unroll
            for (int q = 0; q < 4; q++) acc[mt][nt][q] = 0.f;

    int st = 0, stLoad = 2;
    for (int kt = 0; kt < NKT; kt++) {
        CP_WAIT1();
        __syncthreads();
        const int nk = kt + STAGES - 1;
        if (nk < NKT) load_stage(stLoad, nk);
        CP_COMMIT();

        const uint32_t aS = aU + st * A_STAGE_BYTES;
        const uint32_t bS = bU + st * B_STAGE_BYTES;

        #pragma unroll
        for (int s = 0; s < 2; s++) {
            uint32_t ar[2][4];
            #pragma unroll
            for (int mt = 0; mt < 2; mt++) ldm4(ar[mt], aS + offA[s][mt]);
            uint32_t br[4][4];
            #pragma unroll
            for (int np = 0; np < 4; np++) ldm4(br[np], bS + offB[s][np]);
            #pragma unroll
            for (int mt = 0; mt < 2; mt++)
                #pragma unroll
                for (int np = 0; np < 4; np++) {
                    mma16816(acc[mt][np * 2 + 0], ar[mt], br[np][0], br[np][1]);
                    mma16816(acc[mt][np * 2 + 1], ar[mt], br[np][2], br[np][3]);
                }
        }
        st = (st == STAGES - 1) ? 0 : st + 1;
        stLoad = (stLoad == STAGES - 1) ? 0 : stLoad + 1;
    }

    CP_WAIT0();
    __syncthreads();
    unsigned* cbuf = (unsigned*)sA;

    const int g = lane >> 2;
    const int sub = lane & 3;

    #pragma unroll
    for (int mt = 0; mt < 2; mt++) {
        #pragma unroll
        for (int h = 0; h < 2; h++) {
            unsigned a4[4];
            #pragma unroll
            for (int q = 0; q < 4; q++) a4[q] = 0xFFFFFFFFu;
            #pragma unroll
            for (int nt = 0; nt < 8; nt++) {
                #pragma unroll
                for (int j = 0; j < 2; j++) {
                    float v = acc[mt][nt][2 * h + j];
                    unsigned col = (unsigned)(colbase + wn * 64 + nt * 8 + 2 * sub + j);
                    insert4(a4, (fmap(v) & 0xFFFFF000u) | col);
                }
            }
            #pragma unroll
            for (int off = 1; off <= 2; off <<= 1) {
                unsigned b4[4];
                #pragma unroll
                for (int q = 0; q < 4; q++) b4[q] = __shfl_xor_sync(0xffffffffu, a4[q], off);
                merge4(a4, b4);
            }
            const int rloc = wm * 32 + mt * 16 + h * 8 + g;
            if (sub == 0) {
                #pragma unroll
                for (int q = 0; q < 4; q++) cbuf[(wn * 128 + rloc) * 4 + q] = a4[q];
            }
        }
    }
    __syncthreads();

    if (t < 128) {
        unsigned a4[4], b4[4];
        #pragma unroll
        for (int q = 0; q < 4; q++) { a4[q] = cbuf[t * 4 + q]; b4[q] = cbuf[(128 + t) * 4 + q]; }
        merge4(a4, b4);
        uint4* dst = (uint4*)(g_tilecand + ((size_t)(rowbase + t) * NTILE + blockIdx.x) * 4);
        *dst = make_uint4(a4[0], a4[1], a4[2], a4[3]);
    }
}

// ---------------- kernel 3: merge + exact rescore (1 warp/cand) + top-4 ---
__global__ void __launch_bounds__(512) select_kernel(const float* __restrict__ x, const float* __restrict__ keys) {
    const int row = blockIdx.x;
    __shared__ float xs[KD];
    __shared__ int cidx[CAND];
    __shared__ unsigned long long ck[CAND];
    const int tid = threadIdx.x, wid = tid >> 5, lane = tid & 31;

    xs[tid] = x[(size_t)row * KD + tid];

    if (wid == 0) {
        unsigned a[16];
        #pragma unroll
        for (int q = 0; q < 16; q++) a[q] = 0xFFFFFFFFu;
        uint4 v = *(const uint4*)(g_tilecand + ((size_t)row * NTILE + lane) * 4);
        insert16(a, v.x); insert16(a, v.y); insert16(a, v.z); insert16(a, v.w);
        #pragma unroll
        for (int off = 16; off; off >>= 1) {
            unsigned b[16];
            #pragma unroll
            for (int q = 0; q < 16; q++) b[q] = __shfl_xor_sync(0xffffffffu, a[q], off);
            merge16(a, b);
        }
        if (lane < 16) cidx[lane] = (int)(a[lane] & 0xFFFu);
    }
    __syncthreads();

    // one warp per candidate: all 16 key rows in flight simultaneously
    {
        const int idx = cidx[wid];
        const float* kr = keys + (size_t)idx * KD;
        float sum = 0.f;
        #pragma unroll
        for (int j = 0; j < 16; j++) sum = fmaf(xs[lane + 32 * j], kr[lane + 32 * j], sum);
        #pragma unroll
        for (int o = 16; o; o >>= 1) sum += __shfl_xor_sync(0xffffffffu, sum, o);
        if (lane == 0) {
            float sc = sum * g_invk[idx];
            ck[wid] = ((unsigned long long)fmap(sc) << 32) | (unsigned)idx;
        }
    }
    __syncthreads();
    if (tid == 0) {
        #pragma unroll
        for (int q = 0; q < TOPK; q++) {
            unsigned long long best = ~0ull; int bi = 0;
            #pragma unroll
            for (int c = 0; c < CAND; c++) if (ck[c] < best) { best = ck[c]; bi = c; }
            ck[bi] = ~0ull;
            int idx = (int)(best & 0xffffffffu);
            g_topidx[row * TOPK + q] = idx;
            atomicAdd(&g_binCount[idx], 1);
        }
    }
}

// ---------------- kernel 4: exclusive scan over 4096 bins (1 block) -------
__global__ void scan_kernel() {
    __shared__ int ssum[1024];
    const int t = threadIdx.x;
    int4 v = ((const int4*)g_binCount)[t];
    int s = v.x + v.y + v.z + v.w;
    ssum[t] = s;
    __syncthreads();
    for (int off = 1; off < 1024; off <<= 1) {
        int other = 0;
        if (t >= off) other = ssum[t - off];
        __syncthreads();
        if (t >= off) ssum[t] += other;
        __syncthreads();
    }
    int excl = ssum[t] - s;
    int4 st;
    st.x = excl;
    st.y = excl + v.x;
    st.z = excl + v.x + v.y;
    st.w = excl + v.x + v.y + v.z;
    ((int4*)g_binStart)[t] = st;
}

// ---------------- kernel 5: scatter work items by index -------------------
__global__ void scatter_kernel() {
    int w = blockIdx.x * 256 + threadIdx.x;
    int idx = g_topidx[w];
    int pos = atomicAdd(&g_binStart[idx], 1);
    g_order[pos] = w;
}

// ---------------- kernel 6: index-sorted gather ---------------------------
__global__ void gather_kernel(const float* __restrict__ pv, float* __restrict__ out) {
    const int w = g_order[blockIdx.x];
    const int idx = g_topidx[w];
    const float4* src = (const float4*)(pv + (size_t)idx * ROW_ELEMS);
    float4* dst = (float4*)(out + (size_t)w * ROW_ELEMS);
    #pragma unroll 8
    for (int i = threadIdx.x; i < ROW_ELEMS / 4; i += 256)
        __stcs(dst + i, __ldg(src + i));
}

// ---------------- launcher ----------------
extern "C" void kernel_launch(void* const* d_in, const int* in_sizes, int n_in,
                              void* d_out, int out_size) {
    const float* x    = (const float*)d_in[0];   // (4096, 512)
    const float* keys = (const float*)d_in[1];   // (4096, 512)
    const float* pv   = (const float*)d_in[2];   // (4096, 16, 512)
    float* out = (float*)d_out;

    convert_all_kernel<<<1024 + NP / 8 + 16, 256>>>(x, keys);
    coarse_gemm<<<dim3(NP / BN, NB / BM), 256>>>();
    select_kernel<<<NB, 512>>>(x, keys);
    scan_kernel<<<1, 1024>>>();
    scatter_kernel<<<NWORK / 256, 256>>>();
    gather_kernel<<<NWORK, 256>>>(pv, out);
}

// round 14
// speedup vs baseline: 1.0443x; 1.0026x over previous
#include <cuda_runtime.h>
#include <cuda_bf16.h>
#include <stdint.h>
#include <math.h>

// ---------------- problem constants ----------------
#define KD    512
#define TOPK  4
#define ROW_ELEMS 8192
#define NB 4096
#define NP 4096
#define CAND 16
#define NTILE (NP/128)       // 32 column tiles
#define NWORK (NB*TOPK)      // 16384 gather work items

// ---------------- GEMM tiling ----------------
#define BM 128
#define BN 128
#define BK 32
#define STAGES 3
#define NKT (KD/BK)          // 16 k-steps
#define A_STAGE_BYTES (BM*BK*2)   // 8192
#define B_STAGE_BYTES (BN*BK*2)   // 8192

// ---------------- device scratch ----------------
__device__ float g_invk[NP];
__device__ unsigned g_tilecand[(size_t)NB * NTILE * 4];  // 2 MB, u32 keys
__device__ int   g_topidx[NWORK];
__device__ int   g_binCount[NP];
__device__ int   g_binStart[NP];
__device__ int   g_order[NWORK];
__device__ __nv_bfloat16 g_Xb[(size_t)NB * KD];      // 4 MB
__device__ __nv_bfloat16 g_Kb[(size_t)NP * KD];      // 4 MB (pre-scaled by invk)

// ---------------- helpers ----------------
__device__ __forceinline__ uint32_t smem_to_u32(const void* p) {
    uint32_t a;
    asm("{ .reg .u64 t; cvta.to.shared.u64 t, %1; cvt.u32.u64 %0, t; }" : "=r"(a) : "l"(p));
    return a;
}
__device__ __forceinline__ void cp16(uint32_t dst, const void* src) {
    asm volatile("cp.async.cg.shared.global [%0], [%1], 16;" :: "r"(dst), "l"(src) : "memory");
}
#define CP_COMMIT() asm volatile("cp.async.commit_group;" ::: "memory")
#define CP_WAIT1()  asm volatile("cp.async.wait_group 1;" ::: "memory")
#define CP_WAIT0()  asm volatile("cp.async.wait_group 0;" ::: "memory")

__device__ __forceinline__ void ldm4(uint32_t* r, uint32_t a) {
    asm volatile("ldmatrix.sync.aligned.m8n8.x4.shared.b16 {%0,%1,%2,%3}, [%4];"
                 : "=r"(r[0]), "=r"(r[1]), "=r"(r[2]), "=r"(r[3]) : "r"(a));
}
__device__ __forceinline__ void mma16816(float* c, const uint32_t* a, uint32_t b0, uint32_t b1) {
    asm volatile("mma.sync.aligned.m16n8k16.row.col.f32.bf16.bf16.f32 "
                 "{%0,%1,%2,%3}, {%4,%5,%6,%7}, {%8,%9}, {%0,%1,%2,%3};"
                 : "+f"(c[0]), "+f"(c[1]), "+f"(c[2]), "+f"(c[3])
                 : "r"(a[0]), "r"(a[1]), "r"(a[2]), "r"(a[3]), "r"(b0), "r"(b1));
}

// sortable-ascending float map (smallest cos first)
__device__ __forceinline__ unsigned fmap(float v) {
    unsigned u = __float_as_uint(v);
    return (u & 0x80000000u) ? ~u : (u | 0x80000000u);
}

// ---- u32 sorted small-list primitives (ascending, keep smallest) ----
__device__ __forceinline__ void insert4(unsigned (&a)[4], unsigned key) {
    if (key < a[3]) {
        a[3] = key;
        #pragma unroll
        for (int q = 3; q > 0; q--)
            if (a[q] < a[q - 1]) { unsigned t = a[q]; a[q] = a[q - 1]; a[q - 1] = t; }
    }
}
__device__ __forceinline__ void merge4(unsigned (&a)[4], const unsigned (&b)[4]) {
    #pragma unroll
    for (int q = 0; q < 4; q++) { unsigned o = b[3 - q]; if (o < a[q]) a[q] = o; }
    #pragma unroll
    for (int kk = 2; kk >= 1; kk >>= 1)
        #pragma unroll
        for (int i = 0; i < 4; i++)
            if (!(i & kk)) { int j = i | kk; if (a[j] < a[i]) { unsigned t = a[i]; a[i] = a[j]; a[j] = t; } }
}
__device__ __forceinline__ void insert16(unsigned (&a)[16], unsigned key) {
    if (key < a[15]) {
        a[15] = key;
        #pragma unroll
        for (int q = 15; q > 0; q--)
            if (a[q] < a[q - 1]) { unsigned t = a[q]; a[q] = a[q - 1]; a[q - 1] = t; }
    }
}
__device__ __forceinline__ void merge16(unsigned (&a)[16], const unsigned (&b)[16]) {
    #pragma unroll
    for (int q = 0; q < 16; q++) { unsigned o = b[15 - q]; if (o < a[q]) a[q] = o; }
    #pragma unroll
    for (int kk = 8; kk >= 1; kk >>= 1)
        #pragma unroll
        for (int i = 0; i < 16; i++)
            if (!(i & kk)) { int j = i | kk; if (a[j] < a[i]) { unsigned t = a[i]; a[i] = a[j]; a[j] = t; } }
}

__device__ __forceinline__ unsigned pack_bf16(float a, float b) {
    __nv_bfloat16 ha = __float2bfloat16_rn(a);
    __nv_bfloat16 hb = __float2bfloat16_rn(b);
    unsigned short ua = *(unsigned short*)&ha;
    unsigned short ub = *(unsigned short*)&hb;
    return (unsigned)ua | ((unsigned)ub << 16);
}

// ---------------- kernel 1: fused converts + histogram zero --------------
__global__ void convert_all_kernel(const float* __restrict__ x, const float* __restrict__ keys) {
    if (blockIdx.x < 1024) {
        int i = blockIdx.x * 256 + threadIdx.x;
        const float* s = x + (size_t)i * 8;
        float4 f0 = *(const float4*)s;
        float4 f1 = *(const float4*)(s + 4);
        uint4 o;
        o.x = pack_bf16(f0.x, f0.y); o.y = pack_bf16(f0.z, f0.w);
        o.z = pack_bf16(f1.x, f1.y); o.w = pack_bf16(f1.z, f1.w);
        ((uint4*)g_Xb)[i] = o;
    } else if (blockIdx.x < 1536) {
        const int wid = threadIdx.x >> 5, lane = threadIdx.x & 31;
        const int row = (blockIdx.x - 1024) * 8 + wid;
        const float* kr = keys + (size_t)row * KD;
        float4 v[4];
        float s = 0.f;
        #pragma unroll
        for (int c4 = 0; c4 < 4; c4++) {
            v[c4] = *(const float4*)(kr + c4 * 128 + lane * 4);
            s = fmaf(v[c4].x, v[c4].x, s);
            s = fmaf(v[c4].y, v[c4].y, s);
            s = fmaf(v[c4].z, v[c4].z, s);
            s = fmaf(v[c4].w, v[c4].w, s);
        }
        #pragma unroll
        for (int o = 16; o; o >>= 1) s += __shfl_xor_sync(0xffffffffu, s, o);
        double d = (double)fmaxf(s, 1e-12f);
        float iv = (float)(1.0 / sqrt(d));
        if (lane == 0) g_invk[row] = iv;
        uint2* dst = (uint2*)(g_Kb + (size_t)row * KD);
        #pragma unroll
        for (int c4 = 0; c4 < 4; c4++) {
            uint2 o;
            o.x = pack_bf16(v[c4].x * iv, v[c4].y * iv);
            o.y = pack_bf16(v[c4].z * iv, v[c4].w * iv);
            dst[(c4 * 128 + lane * 4) >> 2] = o;
        }
    } else {
        int i = (blockIdx.x - 1536) * 256 + threadIdx.x;
        if (i < NP) g_binCount[i] = 0;
    }
}

// ---------------- kernel 2: coarse bf16 HMMA GEMM + fused per-tile top-4 ----
__global__ void __launch_bounds__(256) coarse_gemm() {
    __shared__ __align__(1024) char sA[STAGES][A_STAGE_BYTES];
    __shared__ __align__(1024) char sB[STAGES][B_STAGE_BYTES];
    const uint32_t aU = smem_to_u32(sA);
    const uint32_t bU = smem_to_u32(sB);
    const int t = threadIdx.x;
    const int rowbase = blockIdx.y * BM;
    const int colbase = blockIdx.x * BN;

    const int r0 = t >> 2, c0 = t & 3;
    const int r1 = (t + 256) >> 2, c1 = (t + 256) & 3;
    const uint32_t sOffA0 = r0 * 64 + (c0 ^ ((r0 >> 1) & 3)) * 16;
    const uint32_t sOffA1 = r1 * 64 + (c1 ^ ((r1 >> 1) & 3)) * 16;
    const __nv_bfloat16* gA0 = g_Xb + (size_t)(rowbase + r0) * KD + c0 * 8;
    const __nv_bfloat16* gA1 = g_Xb + (size_t)(rowbase + r1) * KD + c1 * 8;
    const __nv_bfloat16* gB0 = g_Kb + (size_t)(colbase + r0) * KD + c0 * 8;
    const __nv_bfloat16* gB1 = g_Kb + (size_t)(colbase + r1) * KD + c1 * 8;

    const int wid = t >> 5, lane = t & 31;
    const int wm = wid & 3, wn = wid >> 2;

    uint32_t offA[2][2];
    uint32_t offB[2][4];
    #pragma unroll
    for (int s = 0; s < 2; s++) {
        #pragma unroll
        for (int mt = 0; mt < 2; mt++) {
            int row = wm * 32 + mt * 16 + (lane & 15);
            int cL = 2 * s + (lane >> 4);
            offA[s][mt] = row * 64 + (cL ^ ((row >> 1) & 3)) * 16;
        }
        #pragma unroll
        for (int np = 0; np < 4; np++) {
            int nrow = wn * 64 + np * 16 + (lane & 7) + ((lane >> 4) << 3);
            int cL = 2 * s + ((lane >> 3) & 1);
            offB[s][np] = nrow * 64 + (cL ^ ((nrow >> 1) & 3)) * 16;
        }
    }

    auto load_stage = [&](int st, int kt) {
        const int k0 = kt * BK;
        cp16(aU + st * A_STAGE_BYTES + sOffA0, gA0 + k0);
        cp16(aU + st * A_STAGE_BYTES + sOffA1, gA1 + k0);
        cp16(bU + st * B_STAGE_BYTES + sOffA0, gB0 + k0);
        cp16(bU + st * B_STAGE_BYTES + sOffA1, gB1 + k0);
    };

    load_stage(0, 0); CP_COMMIT();
    load_stage(1, 1); CP_COMMIT();

    float acc[2][8][4];
    #pragma unroll
    for (int mt = 0; mt < 2; mt++)
        #pragma unroll
        for (int nt = 0; nt < 8; nt++)
            #pragma unroll
            for (int q = 0; q < 4; q++) acc[mt][nt][q] = 0.f;

    int st = 0, stLoad = 2;
    for (int kt = 0; kt < NKT; kt++) {
        CP_WAIT1();
        __syncthreads();
        const int nk = kt + STAGES - 1;
        if (nk < NKT) load_stage(stLoad, nk);
        CP_COMMIT();

        const uint32_t aS = aU + st * A_STAGE_BYTES;
        const uint32_t bS = bU + st * B_STAGE_BYTES;

        #pragma unroll
        for (int s = 0; s < 2; s++) {
            uint32_t ar[2][4];
            #pragma unroll
            for (int mt = 0; mt < 2; mt++) ldm4(ar[mt], aS + offA[s][mt]);
            uint32_t br[4][4];
            #pragma unroll
            for (int np = 0; np < 4; np++) ldm4(br[np], bS + offB[s][np]);
            #pragma unroll
            for (int mt = 0; mt < 2; mt++)
                #pragma unroll
                for (int np = 0; np < 4; np++) {
                    mma16816(acc[mt][np * 2 + 0], ar[mt], br[np][0], br[np][1]);
                    mma16816(acc[mt][np * 2 + 1], ar[mt], br[np][2], br[np][3]);
                }
        }
        st = (st == STAGES - 1) ? 0 : st + 1;
        stLoad = (stLoad == STAGES - 1) ? 0 : stLoad + 1;
    }

    CP_WAIT0();
    __syncthreads();
    unsigned* cbuf = (unsigned*)sA;

    const int g = lane >> 2;
    const int sub = lane & 3;

    #pragma unroll
    for (int mt = 0; mt < 2; mt++) {
        #pragma unroll
        for (int h = 0; h < 2; h++) {
            unsigned a4[4];
            #pragma unroll
            for (int q = 0; q < 4; q++) a4[q] = 0xFFFFFFFFu;
            #pragma unroll
            for (int nt = 0; nt < 8; nt++) {
                #pragma unroll
                for (int j = 0; j < 2; j++) {
                    float v = acc[mt][nt][2 * h + j];
                    unsigned col = (unsigned)(colbase + wn * 64 + nt * 8 + 2 * sub + j);
                    insert4(a4, (fmap(v) & 0xFFFFF000u) | col);
                }
            }
            #pragma unroll
            for (int off = 1; off <= 2; off <<= 1) {
                unsigned b4[4];
                #pragma unroll
                for (int q = 0; q < 4; q++) b4[q] = __shfl_xor_sync(0xffffffffu, a4[q], off);
                merge4(a4, b4);
            }
            const int rloc = wm * 32 + mt * 16 + h * 8 + g;
            if (sub == 0) {
                #pragma unroll
                for (int q = 0; q < 4; q++) cbuf[(wn * 128 + rloc) * 4 + q] = a4[q];
            }
        }
    }
    __syncthreads();

    if (t < 128) {
        unsigned a4[4], b4[4];
        #pragma unroll
        for (int q = 0; q < 4; q++) { a4[q] = cbuf[t * 4 + q]; b4[q] = cbuf[(128 + t) * 4 + q]; }
        merge4(a4, b4);
        uint4* dst = (uint4*)(g_tilecand + ((size_t)(rowbase + t) * NTILE + blockIdx.x) * 4);
        *dst = make_uint4(a4[0], a4[1], a4[2], a4[3]);
    }
}

// ---------------- kernel 3: merge + exact rescore (1 warp/cand) + top-4 ---
__global__ void __launch_bounds__(512) select_kernel(const float* __restrict__ x, const float* __restrict__ keys) {
    const int row = blockIdx.x;
    __shared__ float xs[KD];
    __shared__ int cidx[CAND];
    __shared__ unsigned long long ck[CAND];
    const int tid = threadIdx.x, wid = tid >> 5, lane = tid & 31;

    xs[tid] = x[(size_t)row * KD + tid];

    if (wid == 0) {
        unsigned a[16];
        #pragma unroll
        for (int q = 0; q < 16; q++) a[q] = 0xFFFFFFFFu;
        uint4 v = *(const uint4*)(g_tilecand + ((size_t)row * NTILE + lane) * 4);
        insert16(a, v.x); insert16(a, v.y); insert16(a, v.z); insert16(a, v.w);
        #pragma unroll
        for (int off = 16; off; off >>= 1) {
            unsigned b[16];
            #pragma unroll
            for (int q = 0; q < 16; q++) b[q] = __shfl_xor_sync(0xffffffffu, a[q], off);
            merge16(a, b);
        }
        if (lane < 16) cidx[lane] = (int)(a[lane] & 0xFFFu);
    }
    __syncthreads();

    // one warp per candidate: all 16 key rows in flight simultaneously
    {
        const int idx = cidx[wid];
        const float* kr = keys + (size_t)idx * KD;
        float sum = 0.f;
        #pragma unroll
        for (int j = 0; j < 16; j++) sum = fmaf(xs[lane + 32 * j], kr[lane + 32 * j], sum);
        #pragma unroll
        for (int o = 16; o; o >>= 1) sum += __shfl_xor_sync(0xffffffffu, sum, o);
        if (lane == 0) {
            float sc = sum * g_invk[idx];
            ck[wid] = ((unsigned long long)fmap(sc) << 32) | (unsigned)idx;
        }
    }
    __syncthreads();
    if (tid == 0) {
        #pragma unroll
        for (int q = 0; q < TOPK; q++) {
            unsigned long long best = ~0ull; int bi = 0;
            #pragma unroll
            for (int c = 0; c < CAND; c++) if (ck[c] < best) { best = ck[c]; bi = c; }
            ck[bi] = ~0ull;
            int idx = (int)(best & 0xffffffffu);
            g_topidx[row * TOPK + q] = idx;
            atomicAdd(&g_binCount[idx], 1);
        }
    }
}

// ---------------- kernel 4: exclusive scan over 4096 bins (1 block) -------
__global__ void scan_kernel() {
    __shared__ int ssum[1024];
    const int t = threadIdx.x;
    int4 v = ((const int4*)g_binCount)[t];
    int s = v.x + v.y + v.z + v.w;
    ssum[t] = s;
    __syncthreads();
    for (int off = 1; off < 1024; off <<= 1) {
        int other = 0;
        if (t >= off) other = ssum[t - off];
        __syncthreads();
        if (t >= off) ssum[t] += other;
        __syncthreads();
    }
    int excl = ssum[t] - s;
    int4 st;
    st.x = excl;
    st.y = excl + v.x;
    st.z = excl + v.x + v.y;
    st.w = excl + v.x + v.y + v.z;
    ((int4*)g_binStart)[t] = st;
}

// ---------------- kernel 5: scatter work items by index -------------------
__global__ void scatter_kernel() {
    int w = blockIdx.x * 256 + threadIdx.x;
    int idx = g_topidx[w];
    int pos = atomicAdd(&g_binStart[idx], 1);
    g_order[pos] = w;
}

// ---------------- kernel 6: index-sorted gather ---------------------------
__global__ void gather_kernel(const float* __restrict__ pv, float* __restrict__ out) {
    const int w = g_order[blockIdx.x];
    const int idx = g_topidx[w];
    const float4* src = (const float4*)(pv + (size_t)idx * ROW_ELEMS);
    float4* dst = (float4*)(out + (size_t)w * ROW_ELEMS);
    #pragma unroll 8
    for (int i = threadIdx.x; i < ROW_ELEMS / 4; i += 256)
        __stcs(dst + i, __ldg(src + i));
}

// ---------------- launcher ----------------
extern "C" void kernel_launch(void* const* d_in, const int* in_sizes, int n_in,
                              void* d_out, int out_size) {
    const float* x    = (const float*)d_in[0];   // (4096, 512)
    const float* keys = (const float*)d_in[1];   // (4096, 512)
    const float* pv   = (const float*)d_in[2];   // (4096, 16, 512)
    float* out = (float*)d_out;

    convert_all_kernel<<<1024 + NP / 8 + 16, 256>>>(x, keys);
    coarse_gemm<<<dim3(NP / BN, NB / BM), 256>>>();
    select_kernel<<<NB, 512>>>(x, keys);
    scan_kernel<<<1, 1024>>>();
    scatter_kernel<<<NWORK / 256, 256>>>();
    gather_kernel<<<NWORK, 256>>>(pv, out);
}

// round 15
// speedup vs baseline: 1.1489x; 1.1002x over previous
#include <cuda_runtime.h>
#include <cuda_bf16.h>
#include <stdint.h>
#include <math.h>

// ---------------- problem constants ----------------
#define KD    512
#define TOPK  4
#define ROW_ELEMS 8192
#define NB 4096
#define NP 4096
#define CAND 8
#define NTILE (NP/128)       // 32 column tiles
#define NWORK (NB*TOPK)      // 16384 gather work items

// ---------------- GEMM tiling ----------------
#define BM 128
#define BN 128
#define BK 32
#define STAGES 3
#define NKT (KD/BK)          // 16 k-steps
#define A_STAGE_BYTES (BM*BK*2)   // 8192
#define B_STAGE_BYTES (BN*BK*2)   // 8192

// ---------------- device scratch ----------------
__device__ float g_invk[NP];
__device__ unsigned g_tilecand[(size_t)NB * NTILE * 4];  // 2 MB, u32 keys
__device__ int   g_topidx[NWORK];
__device__ int   g_binCount[NP];
__device__ int   g_binStart[NP];
__device__ int   g_order[NWORK];
__device__ __nv_bfloat16 g_Xb[(size_t)NB * KD];      // 4 MB
__device__ __nv_bfloat16 g_Kb[(size_t)NP * KD];      // 4 MB (pre-scaled by invk)

// ---------------- helpers ----------------
__device__ __forceinline__ uint32_t smem_to_u32(const void* p) {
    uint32_t a;
    asm("{ .reg .u64 t; cvta.to.shared.u64 t, %1; cvt.u32.u64 %0, t; }" : "=r"(a) : "l"(p));
    return a;
}
__device__ __forceinline__ void cp16(uint32_t dst, const void* src) {
    asm volatile("cp.async.cg.shared.global [%0], [%1], 16;" :: "r"(dst), "l"(src) : "memory");
}
#define CP_COMMIT() asm volatile("cp.async.commit_group;" ::: "memory")
#define CP_WAIT1()  asm volatile("cp.async.wait_group 1;" ::: "memory")
#define CP_WAIT0()  asm volatile("cp.async.wait_group 0;" ::: "memory")

__device__ __forceinline__ void ldm4(uint32_t* r, uint32_t a) {
    asm volatile("ldmatrix.sync.aligned.m8n8.x4.shared.b16 {%0,%1,%2,%3}, [%4];"
                 : "=r"(r[0]), "=r"(r[1]), "=r"(r[2]), "=r"(r[3]) : "r"(a));
}
__device__ __forceinline__ void mma16816(float* c, const uint32_t* a, uint32_t b0, uint32_t b1) {
    asm volatile("mma.sync.aligned.m16n8k16.row.col.f32.bf16.bf16.f32 "
                 "{%0,%1,%2,%3}, {%4,%5,%6,%7}, {%8,%9}, {%0,%1,%2,%3};"
                 : "+f"(c[0]), "+f"(c[1]), "+f"(c[2]), "+f"(c[3])
                 : "r"(a[0]), "r"(a[1]), "r"(a[2]), "r"(a[3]), "r"(b0), "r"(b1));
}

// sortable-ascending float map (smallest cos first)
__device__ __forceinline__ unsigned fmap(float v) {
    unsigned u = __float_as_uint(v);
    return (u & 0x80000000u) ? ~u : (u | 0x80000000u);
}

// ---- u32 sorted small-list primitives (ascending, keep smallest) ----
__device__ __forceinline__ void insert4(unsigned (&a)[4], unsigned key) {
    if (key < a[3]) {
        a[3] = key;
        #pragma unroll
        for (int q = 3; q > 0; q--)
            if (a[q] < a[q - 1]) { unsigned t = a[q]; a[q] = a[q - 1]; a[q - 1] = t; }
    }
}
__device__ __forceinline__ void merge4(unsigned (&a)[4], const unsigned (&b)[4]) {
    #pragma unroll
    for (int q = 0; q < 4; q++) { unsigned o = b[3 - q]; if (o < a[q]) a[q] = o; }
    #pragma unroll
    for (int kk = 2; kk >= 1; kk >>= 1)
        #pragma unroll
        for (int i = 0; i < 4; i++)
            if (!(i & kk)) { int j = i | kk; if (a[j] < a[i]) { unsigned t = a[i]; a[i] = a[j]; a[j] = t; } }
}
__device__ __forceinline__ void insert8(unsigned (&a)[8], unsigned key) {
    if (key < a[7]) {
        a[7] = key;
        #pragma unroll
        for (int q = 7; q > 0; q--)
            if (a[q] < a[q - 1]) { unsigned t = a[q]; a[q] = a[q - 1]; a[q - 1] = t; }
    }
}
__device__ __forceinline__ void merge8(unsigned (&a)[8], const unsigned (&b)[8]) {
    #pragma unroll
    for (int q = 0; q < 8; q++) { unsigned o = b[7 - q]; if (o < a[q]) a[q] = o; }
    #pragma unroll
    for (int kk = 4; kk >= 1; kk >>= 1)
        #pragma unroll
        for (int i = 0; i < 8; i++)
            if (!(i & kk)) { int j = i | kk; if (a[j] < a[i]) { unsigned t = a[i]; a[i] = a[j]; a[j] = t; } }
}

__device__ __forceinline__ unsigned pack_bf16(float a, float b) {
    __nv_bfloat16 ha = __float2bfloat16_rn(a);
    __nv_bfloat16 hb = __float2bfloat16_rn(b);
    unsigned short ua = *(unsigned short*)&ha;
    unsigned short ub = *(unsigned short*)&hb;
    return (unsigned)ua | ((unsigned)ub << 16);
}

// ---------------- kernel 1: fused converts + histogram zero --------------
__global__ void convert_all_kernel(const float* __restrict__ x, const float* __restrict__ keys) {
    if (blockIdx.x < 1024) {
        int i = blockIdx.x * 256 + threadIdx.x;
        const float* s = x + (size_t)i * 8;
        float4 f0 = *(const float4*)s;
        float4 f1 = *(const float4*)(s + 4);
        uint4 o;
        o.x = pack_bf16(f0.x, f0.y); o.y = pack_bf16(f0.z, f0.w);
        o.z = pack_bf16(f1.x, f1.y); o.w = pack_bf16(f1.z, f1.w);
        ((uint4*)g_Xb)[i] = o;
    } else if (blockIdx.x < 1536) {
        const int wid = threadIdx.x >> 5, lane = threadIdx.x & 31;
        const int row = (blockIdx.x - 1024) * 8 + wid;
        const float* kr = keys + (size_t)row * KD;
        float4 v[4];
        float s = 0.f;
        #pragma unroll
        for (int c4 = 0; c4 < 4; c4++) {
            v[c4] = *(const float4*)(kr + c4 * 128 + lane * 4);
            s = fmaf(v[c4].x, v[c4].x, s);
            s = fmaf(v[c4].y, v[c4].y, s);
            s = fmaf(v[c4].z, v[c4].z, s);
            s = fmaf(v[c4].w, v[c4].w, s);
        }
        #pragma unroll
        for (int o = 16; o; o >>= 1) s += __shfl_xor_sync(0xffffffffu, s, o);
        double d = (double)fmaxf(s, 1e-12f);
        float iv = (float)(1.0 / sqrt(d));
        if (lane == 0) g_invk[row] = iv;
        uint2* dst = (uint2*)(g_Kb + (size_t)row * KD);
        #pragma unroll
        for (int c4 = 0; c4 < 4; c4++) {
            uint2 o;
            o.x = pack_bf16(v[c4].x * iv, v[c4].y * iv);
            o.y = pack_bf16(v[c4].z * iv, v[c4].w * iv);
            dst[(c4 * 128 + lane * 4) >> 2] = o;
        }
    } else {
        int i = (blockIdx.x - 1536) * 256 + threadIdx.x;
        if (i < NP) g_binCount[i] = 0;
    }
}

// ---------------- kernel 2: coarse bf16 HMMA GEMM + fused per-tile top-4 ----
__global__ void __launch_bounds__(256) coarse_gemm() {
    __shared__ __align__(1024) char sA[STAGES][A_STAGE_BYTES];
    __shared__ __align__(1024) char sB[STAGES][B_STAGE_BYTES];
    const uint32_t aU = smem_to_u32(sA);
    const uint32_t bU = smem_to_u32(sB);
    const int t = threadIdx.x;
    const int rowbase = blockIdx.y * BM;
    const int colbase = blockIdx.x * BN;

    const int r0 = t >> 2, c0 = t & 3;
    const int r1 = (t + 256) >> 2, c1 = (t + 256) & 3;
    const uint32_t sOffA0 = r0 * 64 + (c0 ^ ((r0 >> 1) & 3)) * 16;
    const uint32_t sOffA1 = r1 * 64 + (c1 ^ ((r1 >> 1) & 3)) * 16;
    const __nv_bfloat16* gA0 = g_Xb + (size_t)(rowbase + r0) * KD + c0 * 8;
    const __nv_bfloat16* gA1 = g_Xb + (size_t)(rowbase + r1) * KD + c1 * 8;
    const __nv_bfloat16* gB0 = g_Kb + (size_t)(colbase + r0) * KD + c0 * 8;
    const __nv_bfloat16* gB1 = g_Kb + (size_t)(colbase + r1) * KD + c1 * 8;

    const int wid = t >> 5, lane = t & 31;
    const int wm = wid & 3, wn = wid >> 2;

    uint32_t offA[2][2];
    uint32_t offB[2][4];
    #pragma unroll
    for (int s = 0; s < 2; s++) {
        #pragma unroll
        for (int mt = 0; mt < 2; mt++) {
            int row = wm * 32 + mt * 16 + (lane & 15);
            int cL = 2 * s + (lane >> 4);
            offA[s][mt] = row * 64 + (cL ^ ((row >> 1) & 3)) * 16;
        }
        #pragma unroll
        for (int np = 0; np < 4; np++) {
            int nrow = wn * 64 + np * 16 + (lane & 7) + ((lane >> 4) << 3);
            int cL = 2 * s + ((lane >> 3) & 1);
            offB[s][np] = nrow * 64 + (cL ^ ((nrow >> 1) & 3)) * 16;
        }
    }

    auto load_stage = [&](int st, int kt) {
        const int k0 = kt * BK;
        cp16(aU + st * A_STAGE_BYTES + sOffA0, gA0 + k0);
        cp16(aU + st * A_STAGE_BYTES + sOffA1, gA1 + k0);
        cp16(bU + st * B_STAGE_BYTES + sOffA0, gB0 + k0);
        cp16(bU + st * B_STAGE_BYTES + sOffA1, gB1 + k0);
    };

    load_stage(0, 0); CP_COMMIT();
    load_stage(1, 1); CP_COMMIT();

    float acc[2][8][4];
    #pragma unroll
    for (int mt = 0; mt < 2; mt++)
        #pragma unroll
        for (int nt = 0; nt < 8; nt++)
            #pragma unroll
            for (int q = 0; q < 4; q++) acc[mt][nt][q] = 0.f;

    int st = 0, stLoad = 2;
    for (int kt = 0; kt < NKT; kt++) {
        CP_WAIT1();
        __syncthreads();
        const int nk = kt + STAGES - 1;
        if (nk < NKT) load_stage(stLoad, nk);
        CP_COMMIT();

        const uint32_t aS = aU + st * A_STAGE_BYTES;
        const uint32_t bS = bU + st * B_STAGE_BYTES;

        #pragma unroll
        for (int s = 0; s < 2; s++) {
            uint32_t ar[2][4];
            #pragma unroll
            for (int mt = 0; mt < 2; mt++) ldm4(ar[mt], aS + offA[s][mt]);
            uint32_t br[4][4];
            #pragma unroll
            for (int np = 0; np < 4; np++) ldm4(br[np], bS + offB[s][np]);
            #pragma unroll
            for (int mt = 0; mt < 2; mt++)
                #pragma unroll
                for (int np = 0; np < 4; np++) {
                    mma16816(acc[mt][np * 2 + 0], ar[mt], br[np][0], br[np][1]);
                    mma16816(acc[mt][np * 2 + 1], ar[mt], br[np][2], br[np][3]);
                }
        }
        st = (st == STAGES - 1) ? 0 : st + 1;
        stLoad = (stLoad == STAGES - 1) ? 0 : stLoad + 1;
    }

    CP_WAIT0();
    __syncthreads();
    unsigned* cbuf = (unsigned*)sA;

    const int g = lane >> 2;
    const int sub = lane & 3;

    #pragma unroll
    for (int mt = 0; mt < 2; mt++) {
        #pragma unroll
        for (int h = 0; h < 2; h++) {
            unsigned a4[4];
            #pragma unroll
            for (int q = 0; q < 4; q++) a4[q] = 0xFFFFFFFFu;
            #pragma unroll
            for (int nt = 0; nt < 8; nt++) {
                #pragma unroll
                for (int j = 0; j < 2; j++) {
                    float v = acc[mt][nt][2 * h + j];
                    unsigned col = (unsigned)(colbase + wn * 64 + nt * 8 + 2 * sub + j);
                    insert4(a4, (fmap(v) & 0xFFFFF000u) | col);
                }
            }
            #pragma unroll
            for (int off = 1; off <= 2; off <<= 1) {
                unsigned b4[4];
                #pragma unroll
                for (int q = 0; q < 4; q++) b4[q] = __shfl_xor_sync(0xffffffffu, a4[q], off);
                merge4(a4, b4);
            }
            const int rloc = wm * 32 + mt * 16 + h * 8 + g;
            if (sub == 0) {
                #pragma unroll
                for (int q = 0; q < 4; q++) cbuf[(wn * 128 + rloc) * 4 + q] = a4[q];
            }
        }
    }
    __syncthreads();

    if (t < 128) {
        unsigned a4[4], b4[4];
        #pragma unroll
        for (int q = 0; q < 4; q++) { a4[q] = cbuf[t * 4 + q]; b4[q] = cbuf[(128 + t) * 4 + q]; }
        merge4(a4, b4);
        uint4* dst = (uint4*)(g_tilecand + ((size_t)(rowbase + t) * NTILE + blockIdx.x) * 4);
        *dst = make_uint4(a4[0], a4[1], a4[2], a4[3]);
    }
}

// ---------------- kernel 3: merge top-8 + exact fp32 rescore + top-4 ------
__global__ void select_kernel(const float* __restrict__ x, const float* __restrict__ keys) {
    const int row = blockIdx.x;
    __shared__ float xs[KD];
    __shared__ int cidx[CAND];
    __shared__ unsigned long long ck[CAND];
    const int tid = threadIdx.x, wid = tid >> 5, lane = tid & 31;

    *(float4*)&xs[tid * 4] = *(const float4*)(x + (size_t)row * KD + tid * 4);

    if (wid == 0) {
        // merge 32 tiles x 4 keys -> coarse top-8
        unsigned a[8];
        #pragma unroll
        for (int q = 0; q < 8; q++) a[q] = 0xFFFFFFFFu;
        uint4 v = *(const uint4*)(g_tilecand + ((size_t)row * NTILE + lane) * 4);
        insert8(a, v.x); insert8(a, v.y); insert8(a, v.z); insert8(a, v.w);
        #pragma unroll
        for (int off = 16; off; off >>= 1) {
            unsigned b[8];
            #pragma unroll
            for (int q = 0; q < 8; q++) b[q] = __shfl_xor_sync(0xffffffffu, a[q], off);
            merge8(a, b);
        }
        if (lane < CAND) cidx[lane] = (int)(a[lane] & 0xFFFu);
    }
    __syncthreads();

    for (int c = wid; c < CAND; c += 4) {
        const int idx = cidx[c];
        const float* kr = keys + (size_t)idx * KD;
        float sum = 0.f;
        #pragma unroll
        for (int j = 0; j < 16; j++) sum = fmaf(xs[lane + 32 * j], kr[lane + 32 * j], sum);
        #pragma unroll
        for (int o = 16; o; o >>= 1) sum += __shfl_xor_sync(0xffffffffu, sum, o);
        if (lane == 0) {
            float sc = sum * g_invk[idx];
            ck[c] = ((unsigned long long)fmap(sc) << 32) | (unsigned)idx;
        }
    }
    __syncthreads();
    if (tid == 0) {
        #pragma unroll
        for (int q = 0; q < TOPK; q++) {
            unsigned long long best = ~0ull; int bi = 0;
            #pragma unroll
            for (int c = 0; c < CAND; c++) if (ck[c] < best) { best = ck[c]; bi = c; }
            ck[bi] = ~0ull;
            int idx = (int)(best & 0xffffffffu);
            g_topidx[row * TOPK + q] = idx;
            atomicAdd(&g_binCount[idx], 1);
        }
    }
}

// ---------------- kernel 4: exclusive scan over 4096 bins (1 block) -------
__global__ void scan_kernel() {
    __shared__ int ssum[1024];
    const int t = threadIdx.x;
    int4 v = ((const int4*)g_binCount)[t];
    int s = v.x + v.y + v.z + v.w;
    ssum[t] = s;
    __syncthreads();
    for (int off = 1; off < 1024; off <<= 1) {
        int other = 0;
        if (t >= off) other = ssum[t - off];
        __syncthreads();
        if (t >= off) ssum[t] += other;
        __syncthreads();
    }
    int excl = ssum[t] - s;
    int4 st;
    st.x = excl;
    st.y = excl + v.x;
    st.z = excl + v.x + v.y;
    st.w = excl + v.x + v.y + v.z;
    ((int4*)g_binStart)[t] = st;
}

// ---------------- kernel 5: scatter work items by index -------------------
__global__ void scatter_kernel() {
    int w = blockIdx.x * 256 + threadIdx.x;
    int idx = g_topidx[w];
    int pos = atomicAdd(&g_binStart[idx], 1);
    g_order[pos] = w;
}

// ---------------- kernel 6: index-sorted gather ---------------------------
__global__ void gather_kernel(const float* __restrict__ pv, float* __restrict__ out) {
    const int w = g_order[blockIdx.x];
    const int idx = g_topidx[w];
    const float4* src = (const float4*)(pv + (size_t)idx * ROW_ELEMS);
    float4* dst = (float4*)(out + (size_t)w * ROW_ELEMS);
    #pragma unroll 8
    for (int i = threadIdx.x; i < ROW_ELEMS / 4; i += 256)
        __stcs(dst + i, __ldg(src + i));
}

// ---------------- launcher ----------------
extern "C" void kernel_launch(void* const* d_in, const int* in_sizes, int n_in,
                              void* d_out, int out_size) {
    const float* x    = (const float*)d_in[0];   // (4096, 512)
    const float* keys = (const float*)d_in[1];   // (4096, 512)
    const float* pv   = (const float*)d_in[2];   // (4096, 16, 512)
    float* out = (float*)d_out;

    convert_all_kernel<<<1024 + NP / 8 + 16, 256>>>(x, keys);
    coarse_gemm<<<dim3(NP / BN, NB / BM), 256>>>();
    select_kernel<<<NB, 128>>>(x, keys);
    scan_kernel<<<1, 1024>>>();
    scatter_kernel<<<NWORK / 256, 256>>>();
    gather_kernel<<<NWORK, 256>>>(pv, out);
}

// round 16
// speedup vs baseline: 1.1530x; 1.0035x over previous
#include <cuda_runtime.h>
#include <cuda_bf16.h>
#include <stdint.h>
#include <math.h>

// ---------------- problem constants ----------------
#define KD    512
#define TOPK  4
#define ROW_ELEMS 8192
#define NB 4096
#define NP 4096
#define CAND 8
#define NTILE (NP/128)       // 32 column tiles
#define NWORK (NB*TOPK)      // 16384 gather work items

// ---------------- GEMM tiling ----------------
#define BM 128
#define BN 128
#define BK 32
#define STAGES 3
#define NKT (KD/BK)          // 16 k-steps
#define A_STAGE_BYTES (BM*BK*2)   // 8192
#define B_STAGE_BYTES (BN*BK*2)   // 8192

// ---------------- device scratch ----------------
__device__ float g_invk[NP];
__device__ unsigned g_tilecand[(size_t)NB * NTILE * 4];  // 2 MB, u32 keys
__device__ int   g_topidx[NWORK];
__device__ int   g_binCount[NP];
__device__ int   g_binStart[NP];
__device__ int   g_order[NWORK];
__device__ __nv_bfloat16 g_Xb[(size_t)NB * KD];      // 4 MB
__device__ __nv_bfloat16 g_Kb[(size_t)NP * KD];      // 4 MB (pre-scaled by invk)

// ---------------- helpers ----------------
__device__ __forceinline__ uint32_t smem_to_u32(const void* p) {
    uint32_t a;
    asm("{ .reg .u64 t; cvta.to.shared.u64 t, %1; cvt.u32.u64 %0, t; }" : "=r"(a) : "l"(p));
    return a;
}
__device__ __forceinline__ void cp16(uint32_t dst, const void* src) {
    asm volatile("cp.async.cg.shared.global [%0], [%1], 16;" :: "r"(dst), "l"(src) : "memory");
}
#define CP_COMMIT() asm volatile("cp.async.commit_group;" ::: "memory")
#define CP_WAIT1()  asm volatile("cp.async.wait_group 1;" ::: "memory")
#define CP_WAIT0()  asm volatile("cp.async.wait_group 0;" ::: "memory")

__device__ __forceinline__ void ldm4(uint32_t* r, uint32_t a) {
    asm volatile("ldmatrix.sync.aligned.m8n8.x4.shared.b16 {%0,%1,%2,%3}, [%4];"
                 : "=r"(r[0]), "=r"(r[1]), "=r"(r[2]), "=r"(r[3]) : "r"(a));
}
__device__ __forceinline__ void mma16816(float* c, const uint32_t* a, uint32_t b0, uint32_t b1) {
    asm volatile("mma.sync.aligned.m16n8k16.row.col.f32.bf16.bf16.f32 "
                 "{%0,%1,%2,%3}, {%4,%5,%6,%7}, {%8,%9}, {%0,%1,%2,%3};"
                 : "+f"(c[0]), "+f"(c[1]), "+f"(c[2]), "+f"(c[3])
                 : "r"(a[0]), "r"(a[1]), "r"(a[2]), "r"(a[3]), "r"(b0), "r"(b1));
}

// sortable-ascending float map (smallest cos first)
__device__ __forceinline__ unsigned fmap(float v) {
    unsigned u = __float_as_uint(v);
    return (u & 0x80000000u) ? ~u : (u | 0x80000000u);
}

// ---- u32 sorted small-list primitives (ascending, keep smallest) ----
__device__ __forceinline__ void insert4(unsigned (&a)[4], unsigned key) {
    if (key < a[3]) {
        a[3] = key;
        #pragma unroll
        for (int q = 3; q > 0; q--)
            if (a[q] < a[q - 1]) { unsigned t = a[q]; a[q] = a[q - 1]; a[q - 1] = t; }
    }
}
__device__ __forceinline__ void merge4(unsigned (&a)[4], const unsigned (&b)[4]) {
    #pragma unroll
    for (int q = 0; q < 4; q++) { unsigned o = b[3 - q]; if (o < a[q]) a[q] = o; }
    #pragma unroll
    for (int kk = 2; kk >= 1; kk >>= 1)
        #pragma unroll
        for (int i = 0; i < 4; i++)
            if (!(i & kk)) { int j = i | kk; if (a[j] < a[i]) { unsigned t = a[i]; a[i] = a[j]; a[j] = t; } }
}
__device__ __forceinline__ void insert8(unsigned (&a)[8], unsigned key) {
    if (key < a[7]) {
        a[7] = key;
        #pragma unroll
        for (int q = 7; q > 0; q--)
            if (a[q] < a[q - 1]) { unsigned t = a[q]; a[q] = a[q - 1]; a[q - 1] = t; }
    }
}
__device__ __forceinline__ void merge8(unsigned (&a)[8], const unsigned (&b)[8]) {
    #pragma unroll
    for (int q = 0; q < 8; q++) { unsigned o = b[7 - q]; if (o < a[q]) a[q] = o; }
    #pragma unroll
    for (int kk = 4; kk >= 1; kk >>= 1)
        #pragma unroll
        for (int i = 0; i < 8; i++)
            if (!(i & kk)) { int j = i | kk; if (a[j] < a[i]) { unsigned t = a[i]; a[i] = a[j]; a[j] = t; } }
}

__device__ __forceinline__ unsigned pack_bf16(float a, float b) {
    __nv_bfloat16 ha = __float2bfloat16_rn(a);
    __nv_bfloat16 hb = __float2bfloat16_rn(b);
    unsigned short ua = *(unsigned short*)&ha;
    unsigned short ub = *(unsigned short*)&hb;
    return (unsigned)ua | ((unsigned)ub << 16);
}

// ---------------- kernel 1: fused converts + histogram zero --------------
__global__ void convert_all_kernel(const float* __restrict__ x, const float* __restrict__ keys) {
    if (blockIdx.x < 1024) {
        int i = blockIdx.x * 256 + threadIdx.x;
        const float* s = x + (size_t)i * 8;
        float4 f0 = *(const float4*)s;
        float4 f1 = *(const float4*)(s + 4);
        uint4 o;
        o.x = pack_bf16(f0.x, f0.y); o.y = pack_bf16(f0.z, f0.w);
        o.z = pack_bf16(f1.x, f1.y); o.w = pack_bf16(f1.z, f1.w);
        ((uint4*)g_Xb)[i] = o;
    } else if (blockIdx.x < 1536) {
        const int wid = threadIdx.x >> 5, lane = threadIdx.x & 31;
        const int row = (blockIdx.x - 1024) * 8 + wid;
        const float* kr = keys + (size_t)row * KD;
        float4 v[4];
        float s = 0.f;
        #pragma unroll
        for (int c4 = 0; c4 < 4; c4++) {
            v[c4] = *(const float4*)(kr + c4 * 128 + lane * 4);
            s = fmaf(v[c4].x, v[c4].x, s);
            s = fmaf(v[c4].y, v[c4].y, s);
            s = fmaf(v[c4].z, v[c4].z, s);
            s = fmaf(v[c4].w, v[c4].w, s);
        }
        #pragma unroll
        for (int o = 16; o; o >>= 1) s += __shfl_xor_sync(0xffffffffu, s, o);
        double d = (double)fmaxf(s, 1e-12f);
        float iv = (float)(1.0 / sqrt(d));
        if (lane == 0) g_invk[row] = iv;
        uint2* dst = (uint2*)(g_Kb + (size_t)row * KD);
        #pragma unroll
        for (int c4 = 0; c4 < 4; c4++) {
            uint2 o;
            o.x = pack_bf16(v[c4].x * iv, v[c4].y * iv);
            o.y = pack_bf16(v[c4].z * iv, v[c4].w * iv);
            dst[(c4 * 128 + lane * 4) >> 2] = o;
        }
    } else {
        int i = (blockIdx.x - 1536) * 256 + threadIdx.x;
        if (i < NP) g_binCount[i] = 0;
    }
}

// ---------------- kernel 2: coarse bf16 HMMA GEMM + fused per-tile top-4 ----
__global__ void __launch_bounds__(256) coarse_gemm() {
    __shared__ __align__(1024) char sA[STAGES][A_STAGE_BYTES];
    __shared__ __align__(1024) char sB[STAGES][B_STAGE_BYTES];
    const uint32_t aU = smem_to_u32(sA);
    const uint32_t bU = smem_to_u32(sB);
    const int t = threadIdx.x;
    const int rowbase = blockIdx.y * BM;
    const int colbase = blockIdx.x * BN;

    const int r0 = t >> 2, c0 = t & 3;
    const int r1 = (t + 256) >> 2, c1 = (t + 256) & 3;
    const uint32_t sOffA0 = r0 * 64 + (c0 ^ ((r0 >> 1) & 3)) * 16;
    const uint32_t sOffA1 = r1 * 64 + (c1 ^ ((r1 >> 1) & 3)) * 16;
    const __nv_bfloat16* gA0 = g_Xb + (size_t)(rowbase + r0) * KD + c0 * 8;
    const __nv_bfloat16* gA1 = g_Xb + (size_t)(rowbase + r1) * KD + c1 * 8;
    const __nv_bfloat16* gB0 = g_Kb + (size_t)(colbase + r0) * KD + c0 * 8;
    const __nv_bfloat16* gB1 = g_Kb + (size_t)(colbase + r1) * KD + c1 * 8;

    const int wid = t >> 5, lane = t & 31;
    const int wm = wid & 3, wn = wid >> 2;

    uint32_t offA[2][2];
    uint32_t offB[2][4];
    #pragma unroll
    for (int s = 0; s < 2; s++) {
        #pragma unroll
        for (int mt = 0; mt < 2; mt++) {
            int row = wm * 32 + mt * 16 + (lane & 15);
            int cL = 2 * s + (lane >> 4);
            offA[s][mt] = row * 64 + (cL ^ ((row >> 1) & 3)) * 16;
        }
        #pragma unroll
        for (int np = 0; np < 4; np++) {
            int nrow = wn * 64 + np * 16 + (lane & 7) + ((lane >> 4) << 3);
            int cL = 2 * s + ((lane >> 3) & 1);
            offB[s][np] = nrow * 64 + (cL ^ ((nrow >> 1) & 3)) * 16;
        }
    }

    auto load_stage = [&](int st, int kt) {
        const int k0 = kt * BK;
        cp16(aU + st * A_STAGE_BYTES + sOffA0, gA0 + k0);
        cp16(aU + st * A_STAGE_BYTES + sOffA1, gA1 + k0);
        cp16(bU + st * B_STAGE_BYTES + sOffA0, gB0 + k0);
        cp16(bU + st * B_STAGE_BYTES + sOffA1, gB1 + k0);
    };

    load_stage(0, 0); CP_COMMIT();
    load_stage(1, 1); CP_COMMIT();

    float acc[2][8][4];
    #pragma unroll
    for (int mt = 0; mt < 2; mt++)
        #pragma unroll
        for (int nt = 0; nt < 8; nt++)
            #pragma unroll
            for (int q = 0; q < 4; q++) acc[mt][nt][q] = 0.f;

    int st = 0, stLoad = 2;
    for (int kt = 0; kt < NKT; kt++) {
        CP_WAIT1();
        __syncthreads();
        const int nk = kt + STAGES - 1;
        if (nk < NKT) load_stage(stLoad, nk);
        CP_COMMIT();

        const uint32_t aS = aU + st * A_STAGE_BYTES;
        const uint32_t bS = bU + st * B_STAGE_BYTES;

        // issue ALL fragment loads for both k16 sub-steps up front, then MMA —
        // s=1 LDSMs land while s=0 HMMAs execute
        uint32_t ar[2][2][4];
        uint32_t br[2][4][4];
        #pragma unroll
        for (int s = 0; s < 2; s++) {
            #pragma unroll
            for (int mt = 0; mt < 2; mt++) ldm4(ar[s][mt], aS + offA[s][mt]);
            #pragma unroll
            for (int np = 0; np < 4; np++) ldm4(br[s][np], bS + offB[s][np]);
        }
        #pragma unroll
        for (int s = 0; s < 2; s++)
            #pragma unroll
            for (int mt = 0; mt < 2; mt++)
                #pragma unroll
                for (int np = 0; np < 4; np++) {
                    mma16816(acc[mt][np * 2 + 0], ar[s][mt], br[s][np][0], br[s][np][1]);
                    mma16816(acc[mt][np * 2 + 1], ar[s][mt], br[s][np][2], br[s][np][3]);
                }
        st = (st == STAGES - 1) ? 0 : st + 1;
        stLoad = (stLoad == STAGES - 1) ? 0 : stLoad + 1;
    }

    CP_WAIT0();
    __syncthreads();
    unsigned* cbuf = (unsigned*)sA;

    const int g = lane >> 2;
    const int sub = lane & 3;

    #pragma unroll
    for (int mt = 0; mt < 2; mt++) {
        #pragma unroll
        for (int h = 0; h < 2; h++) {
            unsigned a4[4];
            #pragma unroll
            for (int q = 0; q < 4; q++) a4[q] = 0xFFFFFFFFu;
            #pragma unroll
            for (int nt = 0; nt < 8; nt++) {
                #pragma unroll
                for (int j = 0; j < 2; j++) {
                    float v = acc[mt][nt][2 * h + j];
                    unsigned col = (unsigned)(colbase + wn * 64 + nt * 8 + 2 * sub + j);
                    insert4(a4, (fmap(v) & 0xFFFFF000u) | col);
                }
            }
            #pragma unroll
            for (int off = 1; off <= 2; off <<= 1) {
                unsigned b4[4];
                #pragma unroll
                for (int q = 0; q < 4; q++) b4[q] = __shfl_xor_sync(0xffffffffu, a4[q], off);
                merge4(a4, b4);
            }
            const int rloc = wm * 32 + mt * 16 + h * 8 + g;
            if (sub == 0) {
                #pragma unroll
                for (int q = 0; q < 4; q++) cbuf[(wn * 128 + rloc) * 4 + q] = a4[q];
            }
        }
    }
    __syncthreads();

    if (t < 128) {
        unsigned a4[4], b4[4];
        #pragma unroll
        for (int q = 0; q < 4; q++) { a4[q] = cbuf[t * 4 + q]; b4[q] = cbuf[(128 + t) * 4 + q]; }
        merge4(a4, b4);
        uint4* dst = (uint4*)(g_tilecand + ((size_t)(rowbase + t) * NTILE + blockIdx.x) * 4);
        *dst = make_uint4(a4[0], a4[1], a4[2], a4[3]);
    }
}

// ---------------- kernel 3: merge top-8 + exact fp32 rescore + top-4 ------
__global__ void select_kernel(const float* __restrict__ x, const float* __restrict__ keys) {
    const int row = blockIdx.x;
    __shared__ float xs[KD];
    __shared__ int cidx[CAND];
    __shared__ unsigned long long ck[CAND];
    const int tid = threadIdx.x, wid = tid >> 5, lane = tid & 31;

    *(float4*)&xs[tid * 4] = *(const float4*)(x + (size_t)row * KD + tid * 4);

    if (wid == 0) {
        unsigned a[8];
        #pragma unroll
        for (int q = 0; q < 8; q++) a[q] = 0xFFFFFFFFu;
        uint4 v = *(const uint4*)(g_tilecand + ((size_t)row * NTILE + lane) * 4);
        insert8(a, v.x); insert8(a, v.y); insert8(a, v.z); insert8(a, v.w);
        #pragma unroll
        for (int off = 16; off; off >>= 1) {
            unsigned b[8];
            #pragma unroll
            for (int q = 0; q < 8; q++) b[q] = __shfl_xor_sync(0xffffffffu, a[q], off);
            merge8(a, b);
        }
        if (lane < CAND) cidx[lane] = (int)(a[lane] & 0xFFFu);
    }
    __syncthreads();

    for (int c = wid; c < CAND; c += 4) {
        const int idx = cidx[c];
        const float* kr = keys + (size_t)idx * KD;
        float sum = 0.f;
        #pragma unroll
        for (int j = 0; j < 16; j++) sum = fmaf(xs[lane + 32 * j], kr[lane + 32 * j], sum);
        #pragma unroll
        for (int o = 16; o; o >>= 1) sum += __shfl_xor_sync(0xffffffffu, sum, o);
        if (lane == 0) {
            float sc = sum * g_invk[idx];
            ck[c] = ((unsigned long long)fmap(sc) << 32) | (unsigned)idx;
        }
    }
    __syncthreads();
    if (tid == 0) {
        #pragma unroll
        for (int q = 0; q < TOPK; q++) {
            unsigned long long best = ~0ull; int bi = 0;
            #pragma unroll
            for (int c = 0; c < CAND; c++) if (ck[c] < best) { best = ck[c]; bi = c; }
            ck[bi] = ~0ull;
            int idx = (int)(best & 0xffffffffu);
            g_topidx[row * TOPK + q] = idx;
            atomicAdd(&g_binCount[idx], 1);
        }
    }
}

// ---------------- kernel 4: exclusive scan over 4096 bins (1 block) -------
__global__ void scan_kernel() {
    __shared__ int ssum[1024];
    const int t = threadIdx.x;
    int4 v = ((const int4*)g_binCount)[t];
    int s = v.x + v.y + v.z + v.w;
    ssum[t] = s;
    __syncthreads();
    for (int off = 1; off < 1024; off <<= 1) {
        int other = 0;
        if (t >= off) other = ssum[t - off];
        __syncthreads();
        if (t >= off) ssum[t] += other;
        __syncthreads();
    }
    int excl = ssum[t] - s;
    int4 st;
    st.x = excl;
    st.y = excl + v.x;
    st.z = excl + v.x + v.y;
    st.w = excl + v.x + v.y + v.z;
    ((int4*)g_binStart)[t] = st;
}

// ---------------- kernel 5: scatter work items by index -------------------
__global__ void scatter_kernel() {
    int w = blockIdx.x * 256 + threadIdx.x;
    int idx = g_topidx[w];
    int pos = atomicAdd(&g_binStart[idx], 1);
    g_order[pos] = w;
}

// ---------------- kernel 6: index-sorted gather ---------------------------
__global__ void gather_kernel(const float* __restrict__ pv, float* __restrict__ out) {
    const int w = g_order[blockIdx.x];
    const int idx = g_topidx[w];
    const float4* src = (const float4*)(pv + (size_t)idx * ROW_ELEMS);
    float4* dst = (float4*)(out + (size_t)w * ROW_ELEMS);
    #pragma unroll 8
    for (int i = threadIdx.x; i < ROW_ELEMS / 4; i += 256)
        __stcs(dst + i, __ldg(src + i));
}

// ---------------- launcher ----------------
extern "C" void kernel_launch(void* const* d_in, const int* in_sizes, int n_in,
                              void* d_out, int out_size) {
    const float* x    = (const float*)d_in[0];   // (4096, 512)
    const float* keys = (const float*)d_in[1];   // (4096, 512)
    const float* pv   = (const float*)d_in[2];   // (4096, 16, 512)
    float* out = (float*)d_out;

    convert_all_kernel<<<1024 + NP / 8 + 16, 256>>>(x, keys);
    coarse_gemm<<<dim3(NP / BN, NB / BM), 256>>>();
    select_kernel<<<NB, 128>>>(x, keys);
    scan_kernel<<<1, 1024>>>();
    scatter_kernel<<<NWORK / 256, 256>>>();
    gather_kernel<<<NWORK, 256>>>(pv, out);
}

// round 17
// speedup vs baseline: 1.1796x; 1.0231x over previous
#include <cuda_runtime.h>
#include <cuda_bf16.h>
#include <stdint.h>
#include <math.h>

// ---------------- problem constants ----------------
#define KD    512
#define TOPK  4
#define ROW_ELEMS 8192
#define NB 4096
#define NP 4096
#define CAND 8
#define NTILE (NP/128)       // 32 column tiles
#define NWORK (NB*TOPK)      // 16384 gather work items

// ---------------- GEMM tiling ----------------
#define BM 128
#define BN 128
#define BK 32
#define STAGES 4
#define NKT (KD/BK)          // 16 k-steps
#define A_STAGE_BYTES (BM*BK*2)   // 8192
#define B_STAGE_BYTES (BN*BK*2)   // 8192
#define STAGE_BYTES (A_STAGE_BYTES + B_STAGE_BYTES)
#define GEMM_SMEM (STAGES*STAGE_BYTES + 1024)

// ---------------- device scratch ----------------
__device__ float g_invk[NP];
__device__ unsigned g_tilecand[(size_t)NB * NTILE * 4];  // 2 MB, u32 keys
__device__ int   g_topidx[NWORK];
__device__ int   g_binCount[NP];
__device__ int   g_binStart[NP];
__device__ int   g_order[NWORK];
__device__ __nv_bfloat16 g_Xb[(size_t)NB * KD];      // 4 MB
__device__ __nv_bfloat16 g_Kb[(size_t)NP * KD];      // 4 MB (pre-scaled by invk)

// ---------------- helpers ----------------
__device__ __forceinline__ uint32_t smem_to_u32(const void* p) {
    uint32_t a;
    asm("{ .reg .u64 t; cvta.to.shared.u64 t, %1; cvt.u32.u64 %0, t; }" : "=r"(a) : "l"(p));
    return a;
}
__device__ __forceinline__ void cp16(uint32_t dst, const void* src) {
    asm volatile("cp.async.cg.shared.global [%0], [%1], 16;" :: "r"(dst), "l"(src) : "memory");
}
#define CP_COMMIT() asm volatile("cp.async.commit_group;" ::: "memory")
#define CP_WAIT2()  asm volatile("cp.async.wait_group 2;" ::: "memory")
#define CP_WAIT0()  asm volatile("cp.async.wait_group 0;" ::: "memory")

__device__ __forceinline__ void ldm4(uint32_t* r, uint32_t a) {
    asm volatile("ldmatrix.sync.aligned.m8n8.x4.shared.b16 {%0,%1,%2,%3}, [%4];"
                 : "=r"(r[0]), "=r"(r[1]), "=r"(r[2]), "=r"(r[3]) : "r"(a));
}
__device__ __forceinline__ void mma16816(float* c, const uint32_t* a, uint32_t b0, uint32_t b1) {
    asm volatile("mma.sync.aligned.m16n8k16.row.col.f32.bf16.bf16.f32 "
                 "{%0,%1,%2,%3}, {%4,%5,%6,%7}, {%8,%9}, {%0,%1,%2,%3};"
                 : "+f"(c[0]), "+f"(c[1]), "+f"(c[2]), "+f"(c[3])
                 : "r"(a[0]), "r"(a[1]), "r"(a[2]), "r"(a[3]), "r"(b0), "r"(b1));
}

// sortable-ascending float map (smallest cos first)
__device__ __forceinline__ unsigned fmap(float v) {
    unsigned u = __float_as_uint(v);
    return (u & 0x80000000u) ? ~u : (u | 0x80000000u);
}

// ---- u32 sorted small-list primitives (ascending, keep smallest) ----
__device__ __forceinline__ void insert4(unsigned (&a)[4], unsigned key) {
    if (key < a[3]) {
        a[3] = key;
        #pragma unroll
        for (int q = 3; q > 0; q--)
            if (a[q] < a[q - 1]) { unsigned t = a[q]; a[q] = a[q - 1]; a[q - 1] = t; }
    }
}
__device__ __forceinline__ void merge4(unsigned (&a)[4], const unsigned (&b)[4]) {
    #pragma unroll
    for (int q = 0; q < 4; q++) { unsigned o = b[3 - q]; if (o < a[q]) a[q] = o; }
    #pragma unroll
    for (int kk = 2; kk >= 1; kk >>= 1)
        #pragma unroll
        for (int i = 0; i < 4; i++)
            if (!(i & kk)) { int j = i | kk; if (a[j] < a[i]) { unsigned t = a[i]; a[i] = a[j]; a[j] = t; } }
}
__device__ __forceinline__ void insert8(unsigned (&a)[8], unsigned key) {
    if (key < a[7]) {
        a[7] = key;
        #pragma unroll
        for (int q = 7; q > 0; q--)
            if (a[q] < a[q - 1]) { unsigned t = a[q]; a[q] = a[q - 1]; a[q - 1] = t; }
    }
}
__device__ __forceinline__ void merge8(unsigned (&a)[8], const unsigned (&b)[8]) {
    #pragma unroll
    for (int q = 0; q < 8; q++) { unsigned o = b[7 - q]; if (o < a[q]) a[q] = o; }
    #pragma unroll
    for (int kk = 4; kk >= 1; kk >>= 1)
        #pragma unroll
        for (int i = 0; i < 8; i++)
            if (!(i & kk)) { int j = i | kk; if (a[j] < a[i]) { unsigned t = a[i]; a[i] = a[j]; a[j] = t; } }
}

__device__ __forceinline__ unsigned pack_bf16(float a, float b) {
    __nv_bfloat16 ha = __float2bfloat16_rn(a);
    __nv_bfloat16 hb = __float2bfloat16_rn(b);
    unsigned short ua = *(unsigned short*)&ha;
    unsigned short ub = *(unsigned short*)&hb;
    return (unsigned)ua | ((unsigned)ub << 16);
}

// ---------------- kernel 1: fused converts + histogram zero --------------
__global__ void convert_all_kernel(const float* __restrict__ x, const float* __restrict__ keys) {
    if (blockIdx.x < 1024) {
        int i = blockIdx.x * 256 + threadIdx.x;
        const float* s = x + (size_t)i * 8;
        float4 f0 = *(const float4*)s;
        float4 f1 = *(const float4*)(s + 4);
        uint4 o;
        o.x = pack_bf16(f0.x, f0.y); o.y = pack_bf16(f0.z, f0.w);
        o.z = pack_bf16(f1.x, f1.y); o.w = pack_bf16(f1.z, f1.w);
        ((uint4*)g_Xb)[i] = o;
    } else if (blockIdx.x < 1536) {
        const int wid = threadIdx.x >> 5, lane = threadIdx.x & 31;
        const int row = (blockIdx.x - 1024) * 8 + wid;
        const float* kr = keys + (size_t)row * KD;
        float4 v[4];
        float s = 0.f;
        #pragma unroll
        for (int c4 = 0; c4 < 4; c4++) {
            v[c4] = *(const float4*)(kr + c4 * 128 + lane * 4);
            s = fmaf(v[c4].x, v[c4].x, s);
            s = fmaf(v[c4].y, v[c4].y, s);
            s = fmaf(v[c4].z, v[c4].z, s);
            s = fmaf(v[c4].w, v[c4].w, s);
        }
        #pragma unroll
        for (int o = 16; o; o >>= 1) s += __shfl_xor_sync(0xffffffffu, s, o);
        double d = (double)fmaxf(s, 1e-12f);
        float iv = (float)(1.0 / sqrt(d));
        if (lane == 0) g_invk[row] = iv;
        uint2* dst = (uint2*)(g_Kb + (size_t)row * KD);
        #pragma unroll
        for (int c4 = 0; c4 < 4; c4++) {
            uint2 o;
            o.x = pack_bf16(v[c4].x * iv, v[c4].y * iv);
            o.y = pack_bf16(v[c4].z * iv, v[c4].w * iv);
            dst[(c4 * 128 + lane * 4) >> 2] = o;
        }
    } else {
        int i = (blockIdx.x - 1536) * 256 + threadIdx.x;
        if (i < NP) g_binCount[i] = 0;
    }
}

// ---------------- kernel 2: coarse bf16 HMMA GEMM + fused per-tile top-4 ----
// 4-stage ring, loads issued 2 stages ahead BEFORE wait+barrier (no reader in
// the skew-1 window touches stage (kt+2)%4).
__global__ void __launch_bounds__(256) coarse_gemm() {
    extern __shared__ char dynsmem[];
    const uint32_t base = (smem_to_u32(dynsmem) + 1023u) & ~1023u;
    const int t = threadIdx.x;
    const int rowbase = blockIdx.y * BM;
    const int colbase = blockIdx.x * BN;

    const int r0 = t >> 2, c0 = t & 3;
    const int r1 = (t + 256) >> 2, c1 = (t + 256) & 3;
    const uint32_t sOffA0 = r0 * 64 + (c0 ^ ((r0 >> 1) & 3)) * 16;
    const uint32_t sOffA1 = r1 * 64 + (c1 ^ ((r1 >> 1) & 3)) * 16;
    const __nv_bfloat16* gA0 = g_Xb + (size_t)(rowbase + r0) * KD + c0 * 8;
    const __nv_bfloat16* gA1 = g_Xb + (size_t)(rowbase + r1) * KD + c1 * 8;
    const __nv_bfloat16* gB0 = g_Kb + (size_t)(colbase + r0) * KD + c0 * 8;
    const __nv_bfloat16* gB1 = g_Kb + (size_t)(colbase + r1) * KD + c1 * 8;

    const int wid = t >> 5, lane = t & 31;
    const int wm = wid & 3, wn = wid >> 2;

    uint32_t offA[2][2];
    uint32_t offB[2][4];
    #pragma unroll
    for (int s = 0; s < 2; s++) {
        #pragma unroll
        for (int mt = 0; mt < 2; mt++) {
            int row = wm * 32 + mt * 16 + (lane & 15);
            int cL = 2 * s + (lane >> 4);
            offA[s][mt] = row * 64 + (cL ^ ((row >> 1) & 3)) * 16;
        }
        #pragma unroll
        for (int np = 0; np < 4; np++) {
            int nrow = wn * 64 + np * 16 + (lane & 7) + ((lane >> 4) << 3);
            int cL = 2 * s + ((lane >> 3) & 1);
            offB[s][np] = nrow * 64 + (cL ^ ((nrow >> 1) & 3)) * 16;
        }
    }

    auto load_stage = [&](int st, int kt) {
        const int k0 = kt * BK;
        const uint32_t aS = base + st * STAGE_BYTES;
        const uint32_t bS = aS + A_STAGE_BYTES;
        cp16(aS + sOffA0, gA0 + k0);
        cp16(aS + sOffA1, gA1 + k0);
        cp16(bS + sOffA0, gB0 + k0);
        cp16(bS + sOffA1, gB1 + k0);
    };

    // prologue: chunks 0,1 into stages 0,1
    load_stage(0, 0); CP_COMMIT();
    load_stage(1, 1); CP_COMMIT();

    float acc[2][8][4];
    #pragma unroll
    for (int mt = 0; mt < 2; mt++)
        #pragma unroll
        for (int nt = 0; nt < 8; nt++)
            #pragma unroll
            for (int q = 0; q < 4; q++) acc[mt][nt][q] = 0.f;

    int st = 0, stLoad = 2;
    for (int kt = 0; kt < NKT; kt++) {
        // issue loads 2 ahead BEFORE the wait/barrier; commit (possibly empty) group
        const int nk = kt + 2;
        if (nk < NKT) load_stage(stLoad, nk);
        CP_COMMIT();
        CP_WAIT2();          // chunks kt+1, kt+2 may remain in flight
        __syncthreads();

        const uint32_t aS = base + st * STAGE_BYTES;
        const uint32_t bS = aS + A_STAGE_BYTES;

        uint32_t ar[2][2][4];
        uint32_t br[2][4][4];
        #pragma unroll
        for (int s = 0; s < 2; s++) {
            #pragma unroll
            for (int mt = 0; mt < 2; mt++) ldm4(ar[s][mt], aS + offA[s][mt]);
            #pragma unroll
            for (int np = 0; np < 4; np++) ldm4(br[s][np], bS + offB[s][np]);
        }
        #pragma unroll
        for (int s = 0; s < 2; s++)
            #pragma unroll
            for (int mt = 0; mt < 2; mt++)
                #pragma unroll
                for (int np = 0; np < 4; np++) {
                    mma16816(acc[mt][np * 2 + 0], ar[s][mt], br[s][np][0], br[s][np][1]);
                    mma16816(acc[mt][np * 2 + 1], ar[s][mt], br[s][np][2], br[s][np][3]);
                }
        st = (st == STAGES - 1) ? 0 : st + 1;
        stLoad = (stLoad == STAGES - 1) ? 0 : stLoad + 1;
    }

    // ---- fused epilogue: per-row top-4 of this 128x128 tile (u32 keys) ----
    CP_WAIT0();
    __syncthreads();
    unsigned* cbuf = (unsigned*)dynsmem;   // reuse dynamic smem (4 KB)

    const int g = lane >> 2;
    const int sub = lane & 3;

    #pragma unroll
    for (int mt = 0; mt < 2; mt++) {
        #pragma unroll
        for (int h = 0; h < 2; h++) {
            unsigned a4[4];
            #pragma unroll
            for (int q = 0; q < 4; q++) a4[q] = 0xFFFFFFFFu;
            #pragma unroll
            for (int nt = 0; nt < 8; nt++) {
                #pragma unroll
                for (int j = 0; j < 2; j++) {
                    float v = acc[mt][nt][2 * h + j];
                    unsigned col = (unsigned)(colbase + wn * 64 + nt * 8 + 2 * sub + j);
                    insert4(a4, (fmap(v) & 0xFFFFF000u) | col);
                }
            }
            #pragma unroll
            for (int off = 1; off <= 2; off <<= 1) {
                unsigned b4[4];
                #pragma unroll
                for (int q = 0; q < 4; q++) b4[q] = __shfl_xor_sync(0xffffffffu, a4[q], off);
                merge4(a4, b4);
            }
            const int rloc = wm * 32 + mt * 16 + h * 8 + g;
            if (sub == 0) {
                #pragma unroll
                for (int q = 0; q < 4; q++) cbuf[(wn * 128 + rloc) * 4 + q] = a4[q];
            }
        }
    }
    __syncthreads();

    if (t < 128) {
        unsigned a4[4], b4[4];
        #pragma unroll
        for (int q = 0; q < 4; q++) { a4[q] = cbuf[t * 4 + q]; b4[q] = cbuf[(128 + t) * 4 + q]; }
        merge4(a4, b4);
        uint4* dst = (uint4*)(g_tilecand + ((size_t)(rowbase + t) * NTILE + blockIdx.x) * 4);
        *dst = make_uint4(a4[0], a4[1], a4[2], a4[3]);
    }
}

// ---------------- kernel 3: merge top-8 + exact fp32 rescore + top-4 ------
__global__ void select_kernel(const float* __restrict__ x, const float* __restrict__ keys) {
    const int row = blockIdx.x;
    __shared__ float xs[KD];
    __shared__ int cidx[CAND];
    __shared__ unsigned long long ck[CAND];
    const int tid = threadIdx.x, wid = tid >> 5, lane = tid & 31;

    *(float4*)&xs[tid * 4] = *(const float4*)(x + (size_t)row * KD + tid * 4);

    if (wid == 0) {
        unsigned a[8];
        #pragma unroll
        for (int q = 0; q < 8; q++) a[q] = 0xFFFFFFFFu;
        uint4 v = *(const uint4*)(g_tilecand + ((size_t)row * NTILE + lane) * 4);
        insert8(a, v.x); insert8(a, v.y); insert8(a, v.z); insert8(a, v.w);
        #pragma unroll
        for (int off = 16; off; off >>= 1) {
            unsigned b[8];
            #pragma unroll
            for (int q = 0; q < 8; q++) b[q] = __shfl_xor_sync(0xffffffffu, a[q], off);
            merge8(a, b);
        }
        if (lane < CAND) cidx[lane] = (int)(a[lane] & 0xFFFu);
    }
    __syncthreads();

    for (int c = wid; c < CAND; c += 4) {
        const int idx = cidx[c];
        const float* kr = keys + (size_t)idx * KD;
        float sum = 0.f;
        #pragma unroll
        for (int j = 0; j < 16; j++) sum = fmaf(xs[lane + 32 * j], kr[lane + 32 * j], sum);
        #pragma unroll
        for (int o = 16; o; o >>= 1) sum += __shfl_xor_sync(0xffffffffu, sum, o);
        if (lane == 0) {
            float sc = sum * g_invk[idx];
            ck[c] = ((unsigned long long)fmap(sc) << 32) | (unsigned)idx;
        }
    }
    __syncthreads();
    if (tid == 0) {
        #pragma unroll
        for (int q = 0; q < TOPK; q++) {
            unsigned long long best = ~0ull; int bi = 0;
            #pragma unroll
            for (int c = 0; c < CAND; c++) if (ck[c] < best) { best = ck[c]; bi = c; }
            ck[bi] = ~0ull;
            int idx = (int)(best & 0xffffffffu);
            g_topidx[row * TOPK + q] = idx;
            atomicAdd(&g_binCount[idx], 1);
        }
    }
}

// ---------------- kernel 4: shuffle-based exclusive scan (4096 bins) ------
__global__ void scan_kernel() {
    __shared__ int wsum[32];
    const int t = threadIdx.x, lane = t & 31, w = t >> 5;
    int4 v = ((const int4*)g_binCount)[t];
    int s = v.x + v.y + v.z + v.w;
    // warp-inclusive scan
    int inc = s;
    #pragma unroll
    for (int off = 1; off < 32; off <<= 1) {
        int n = __shfl_up_sync(0xffffffffu, inc, off);
        if (lane >= off) inc += n;
    }
    if (lane == 31) wsum[w] = inc;
    __syncthreads();
    if (w == 0) {
        int ws = wsum[lane];
        int wi = ws;
        #pragma unroll
        for (int off = 1; off < 32; off <<= 1) {
            int n = __shfl_up_sync(0xffffffffu, wi, off);
            if (lane >= off) wi += n;
        }
        wsum[lane] = wi - ws;   // exclusive warp-prefix
    }
    __syncthreads();
    int excl = wsum[w] + (inc - s);
    int4 st;
    st.x = excl;
    st.y = excl + v.x;
    st.z = excl + v.x + v.y;
    st.w = excl + v.x + v.y + v.z;
    ((int4*)g_binStart)[t] = st;
}

// ---------------- kernel 5: scatter work items by index -------------------
__global__ void scatter_kernel() {
    int w = blockIdx.x * 256 + threadIdx.x;
    int idx = g_topidx[w];
    int pos = atomicAdd(&g_binStart[idx], 1);
    g_order[pos] = w;
}

// ---------------- kernel 6: index-sorted gather ---------------------------
__global__ void gather_kernel(const float* __restrict__ pv, float* __restrict__ out) {
    const int w = g_order[blockIdx.x];
    const int idx = g_topidx[w];
    const float4* src = (const float4*)(pv + (size_t)idx * ROW_ELEMS);
    float4* dst = (float4*)(out + (size_t)w * ROW_ELEMS);
    #pragma unroll 8
    for (int i = threadIdx.x; i < ROW_ELEMS / 4; i += 256)
        __stcs(dst + i, __ldg(src + i));
}

// ---------------- launcher ----------------
extern "C" void kernel_launch(void* const* d_in, const int* in_sizes, int n_in,
                              void* d_out, int out_size) {
    const float* x    = (const float*)d_in[0];   // (4096, 512)
    const float* keys = (const float*)d_in[1];   // (4096, 512)
    const float* pv   = (const float*)d_in[2];   // (4096, 16, 512)
    float* out = (float*)d_out;

    cudaFuncSetAttribute(coarse_gemm, cudaFuncAttributeMaxDynamicSharedMemorySize, GEMM_SMEM);

    convert_all_kernel<<<1024 + NP / 8 + 16, 256>>>(x, keys);
    coarse_gemm<<<dim3(NP / BN, NB / BM), 256, GEMM_SMEM>>>();
    select_kernel<<<NB, 128>>>(x, keys);
    scan_kernel<<<1, 1024>>>();
    scatter_kernel<<<NWORK / 256, 256>>>();
    gather_kernel<<<NWORK, 256>>>(pv, out);
}